// round 13
// baseline (speedup 1.0000x reference)
#include <cuda_runtime.h>
#include <math.h>

#define N_  256
#define M_  256
#define D_  256
#define E_  128
#define H_  4
#define HD_ 32
#define P_  64
#define CH_ 74    // key chunks per head (variable 3-4 tiles each)

// ---------------- packed fp32x2 helpers (Blackwell FFMA2 path) -----------
typedef unsigned long long u64;

__device__ __forceinline__ u64 pack2(float a, float b) {
    u64 r; asm("mov.b64 %0, {%1, %2};" : "=l"(r) : "f"(a), "f"(b)); return r;
}
__device__ __forceinline__ u64 dup2(float a) {
    u64 r; asm("mov.b64 %0, {%1, %1};" : "=l"(r) : "f"(a)); return r;
}
__device__ __forceinline__ void unpack2(u64 v, float& lo, float& hi) {
    asm("mov.b64 {%0, %1}, %2;" : "=f"(lo), "=f"(hi) : "l"(v));
}
__device__ __forceinline__ u64 fma2(u64 a, u64 b, u64 c) {
    u64 d; asm("fma.rn.f32x2 %0, %1, %2, %3;" : "=l"(d) : "l"(a), "l"(b), "l"(c)); return d;
}
__device__ __forceinline__ u64 add2(u64 a, u64 b) {
    u64 d; asm("add.rn.f32x2 %0, %1, %2;" : "=l"(d) : "l"(a), "l"(b)); return d;
}
__device__ __forceinline__ u64 mul2(u64 a, u64 b) {
    u64 d; asm("mul.rn.f32x2 %0, %1, %2;" : "=l"(d) : "l"(a), "l"(b)); return d;
}

// ---------------- device scratch (static, no allocations) ----------------
__device__ float d_qpe[N_*E_];                     // pos-MLP query embedding
__device__ float d_q[N_*E_];                       // scaled queries [N][E]
__device__ float d_phix[N_*E_], d_nphiy[M_*E_];    // nphiy = NEGATED phi_y
__device__ float d_gx[N_*E_],  d_ngy[M_*E_];       // ngy = NEGATED g_y
__device__ float d_Wkp[E_*P_], d_Wkg[E_*P_];       // folded MLP2 @ proj weights
__device__ float d_bkp[E_],    d_bkg[E_];
__device__ float d_pm[H_*CH_*N_], d_pl[H_*CH_*N_]; // partial softmax stats
__device__ float d_po[H_*CH_*N_*HD_];              // partial outputs

// chunk c tile range: heavy chunks (c<34) have 4 tiles, light have 3
__device__ __forceinline__ void chunk_range(int c, int& t0, int& t1) {
    if (c < 34) { t0 = 4*c;            t1 = t0 + 4; }
    else        { t0 = 136 + 3*(c-34); t1 = t0 + 3; }
}

// ---------------- A0: fold phi_w[:,D:] @ k_w2 -> Wkp / Wkg ---------------
__global__ void kfold(const float* __restrict__ phi_w, const float* __restrict__ g_w,
                      const float* __restrict__ k_w2, const float* __restrict__ k_b2) {
    int e = blockIdx.x, t = threadIdx.x;   // 128 threads
    if (t < 64) {
        float a = 0.f;
        for (int ep = 0; ep < 128; ep++)
            a = fmaf(phi_w[e*384 + 256 + ep], k_w2[ep*64 + t], a);
        d_Wkp[e*64 + t] = a;
    } else {
        int p = t - 64; float a = 0.f;
        for (int ep = 0; ep < 128; ep++)
            a = fmaf(g_w[e*384 + 256 + ep], k_w2[ep*64 + p], a);
        d_Wkg[e*64 + p] = a;
    }
    if (t == 0) {
        float a = 0.f;
        for (int ep = 0; ep < 128; ep++) a = fmaf(phi_w[e*384 + 256 + ep], k_b2[ep], a);
        d_bkp[e] = a;
    }
    if (t == 64) {
        float a = 0.f;
        for (int ep = 0; ep < 128; ep++) a = fmaf(g_w[e*384 + 256 + ep], k_b2[ep], a);
        d_bkg[e] = a;
    }
}

// ---------------- A1: query pos-MLP embedding (coalesced, smem-staged) ---
__global__ void __launch_bounds__(256)
kqpe(const float* __restrict__ x_pos,
     const float* __restrict__ q_w1, const float* __restrict__ q_b1,
     const float* __restrict__ q_w2, const float* __restrict__ q_b2) {
    __shared__ float sW[128*65];   // q_w2 [e][p], pad 65
    __shared__ float hq[32*65];    // hidden [n][p], pad 65
    __shared__ float w1s[192], b1s[64], b2s[128];
    int t = threadIdx.x, n0 = blockIdx.x * 32;

    for (int i = t; i < 8192; i += 256) {
        int e = i >> 6, p = i & 63;
        sW[e*65 + p] = q_w2[i];
    }
    if (t < 192) w1s[t] = q_w1[t];
    if (t < 64)  b1s[t] = q_b1[t];
    if (t < 128) b2s[t] = q_b2[t];
    __syncthreads();

    for (int i = t; i < 2048; i += 256) {
        int n = i >> 6, p = i & 63;
        float xp0 = x_pos[(n0+n)*3], xp1 = x_pos[(n0+n)*3+1], xp2 = x_pos[(n0+n)*3+2];
        hq[n*65 + p] = fmaxf(0.f, fmaf(w1s[p*3], xp0, fmaf(w1s[p*3+1], xp1,
                              fmaf(w1s[p*3+2], xp2, b1s[p]))));
    }
    __syncthreads();

    int ce = t & 31, rg = t >> 5;
    float acc[4][4];
    #pragma unroll
    for (int i = 0; i < 4; i++)
        #pragma unroll
        for (int j = 0; j < 4; j++) acc[i][j] = b2s[ce + 32*j];
    for (int p = 0; p < 64; p++) {
        float w0 = sW[(ce     )*65 + p], w1 = sW[(ce+32)*65 + p];
        float w2 = sW[(ce+64)*65 + p],  w3 = sW[(ce+96)*65 + p];
        #pragma unroll
        for (int i = 0; i < 4; i++) {
            float xv = hq[(rg*4 + i)*65 + p];
            acc[i][0] = fmaf(xv, w0, acc[i][0]);
            acc[i][1] = fmaf(xv, w1, acc[i][1]);
            acc[i][2] = fmaf(xv, w2, acc[i][2]);
            acc[i][3] = fmaf(xv, w3, acc[i][3]);
        }
    }
    #pragma unroll
    for (int i = 0; i < 4; i++)
        #pragma unroll
        for (int j = 0; j < 4; j++)
            d_qpe[(n0 + rg*4 + i)*128 + ce + 32*j] = acc[i][j];
}

// ---------------- A2: tiled GEMM for q / phix / nphiy / gx / ngy ---------
__global__ void __launch_bounds__(256)
kgemm(const float* __restrict__ x, const float* __restrict__ y,
      const float* __restrict__ theta_w, const float* __restrict__ phi_w,
      const float* __restrict__ g_w) {
    __shared__ float ws[128*65];
    __shared__ float xs[32*65];
    int t = threadIdx.x;
    int job = blockIdx.x >> 3, rt = blockIdx.x & 7;
    int n0 = rt * 32;

    const float* W   = (job == 0) ? theta_w : (job <= 2 ? phi_w : g_w);
    const float* src = (job == 2 || job == 4) ? y : x;
    int   K    = (job == 0) ? 384 : 256;
    float mult = (job == 0) ? 0.17677669529663687f
               : (job == 2 || job == 4) ? -1.f : 1.f;
    float* out = (job == 0) ? d_q : (job == 1) ? d_phix : (job == 2) ? d_nphiy
               : (job == 3) ? d_gx : d_ngy;

    int ce = t & 31, rg = t >> 5;
    float acc[4][4];
    #pragma unroll
    for (int i = 0; i < 4; i++)
        #pragma unroll
        for (int j = 0; j < 4; j++) acc[i][j] = 0.f;

    for (int k0 = 0; k0 < K; k0 += 64) {
        for (int i = t; i < 8192; i += 256) {
            int e = i >> 6, k = i & 63;
            ws[e*65 + k] = W[e*384 + k0 + k];
        }
        for (int i = t; i < 2048; i += 256) {
            int n = i >> 6, k = i & 63;
            float v;
            if (job == 0 && k0 >= 256) v = d_qpe[(n0+n)*128 + (k0 - 256) + k];
            else                       v = src[(n0+n)*256 + k0 + k];
            xs[n*65 + k] = v;
        }
        __syncthreads();
        #pragma unroll 4
        for (int k = 0; k < 64; k++) {
            float w0 = ws[(ce     )*65 + k], w1 = ws[(ce+32)*65 + k];
            float w2 = ws[(ce+64)*65 + k],  w3 = ws[(ce+96)*65 + k];
            #pragma unroll
            for (int i = 0; i < 4; i++) {
                float xv = xs[(rg*4 + i)*65 + k];
                acc[i][0] = fmaf(xv, w0, acc[i][0]);
                acc[i][1] = fmaf(xv, w1, acc[i][1]);
                acc[i][2] = fmaf(xv, w2, acc[i][2]);
                acc[i][3] = fmaf(xv, w3, acc[i][3]);
            }
        }
        __syncthreads();
    }
    #pragma unroll
    for (int i = 0; i < 4; i++)
        #pragma unroll
        for (int j = 0; j < 4; j++)
            out[(n0 + rg*4 + i)*128 + ce + 32*j] = acc[i][j] * mult;
}

// ---------------- B: fused kv-gen + flash attention ----------------------
// 256 threads, 296 CTAs. Half-dim split: lanes l and l^16 co-own queries
// {w*32 + (l&15), +16}; each lane holds 16 of the 32 head dims of q and o.
// QK dot completed with one shfl.xor(16) per key. This halves per-thread
// state (o+q = 64 regs) so the kernel fits 128 regs @ 2 CTAs/SM, 16 warps.
__global__ void __launch_bounds__(256, 2)
kattn(const float* __restrict__ x_pos, const float* __restrict__ y_pos,
      const float* __restrict__ k_w1, const float* __restrict__ k_b1) {
    extern __shared__ float sm[];
    float* ks   = sm;            // [256][36]
    float* vs   = sm + 9216;     // [256][36]
    float* WkpT = sm + 18432;    // [64][32]
    float* WkgT = sm + 20480;    // [64][32]
    float* kw1s = sm + 22528;    // [64*3]
    float* kb1s = sm + 22720;    // [64]
    u64*   bkp2 = (u64*)(sm + 22784); // [16]
    u64*   bkg2 = bkp2 + 16;          // [16]   total 91392 bytes

    int bid = blockIdx.x, t = threadIdx.x;
    int c, h;
    if (bid < 136) { c = bid % 34; h = bid / 34; }       // heavy: c in [0,34)
    else {
        int u = bid - 136;                               // u in [0,160)
        c = 34 + (u % 40); h = u / 40;                   // light: c in [34,74)
    }
    int t0, t1; chunk_range(c, t0, t1);

    for (int i = t; i < 2048; i += 256) {
        int p = i >> 5, d = i & 31;
        WkpT[i] = d_Wkp[(h*32 + d)*64 + p];
        WkgT[i] = d_Wkg[(h*32 + d)*64 + p];
    }
    for (int i = t; i < 192; i += 256) kw1s[i] = k_w1[i];
    if (t < 64) kb1s[t] = k_b1[t];
    if (t < 16) bkp2[t] = pack2(d_bkp[h*32 + 2*t], d_bkp[h*32 + 2*t + 1]);
    else if (t < 32) { int j = t - 16; bkg2[j] = pack2(d_bkg[h*32 + 2*j], d_bkg[h*32 + 2*j + 1]); }
    __syncthreads();

    int l = t & 31, w = t >> 5;
    int qcol = l & 15, half = l >> 4;
    int qAi = w*32 + qcol, qBi = qAi + 16;   // the two queries this lane co-owns
    int hoff = half * 16;                    // 16-dim slice within head

    // load q halves once (invariant across tiles)
    u64 qA[8], qB[8];
    {
        const ulonglong2* pa = (const ulonglong2*)(d_q + qAi*E_ + h*HD_ + hoff);
        const ulonglong2* pb = (const ulonglong2*)(d_q + qBi*E_ + h*HD_ + hoff);
        #pragma unroll
        for (int i = 0; i < 4; i++) {
            ulonglong2 v = pa[i]; qA[2*i] = v.x; qA[2*i+1] = v.y;
            ulonglong2 u = pb[i]; qB[2*i] = u.x; qB[2*i+1] = u.y;
        }
    }

    u64 oA[8], oB[8];
    #pragma unroll
    for (int i = 0; i < 8; i++) { oA[i] = 0ULL; oB[i] = 0ULL; }
    float mrA = -INFINITY, lrA = 0.f, mrB = -INFINITY, lrB = 0.f;

    float xp0 = x_pos[t*3], xp1 = x_pos[t*3+1], xp2 = x_pos[t*3+2];

    for (int m = t0; m < t1; ++m) {
        // ---- generate key+value row t of tile m (full 32-dim head slice) ----
        {
            float r0 = xp0 - y_pos[m*3];
            float r1 = xp1 - y_pos[m*3+1];
            float r2 = xp2 - y_pos[m*3+2];

            u64 acc2[16];
            {   // k row
                const ulonglong2* px = (const ulonglong2*)(d_phix  + t*E_ + h*HD_);
                const ulonglong2* py = (const ulonglong2*)(d_nphiy + m*E_ + h*HD_);
                #pragma unroll
                for (int i = 0; i < 8; i++) {
                    ulonglong2 a = px[i], b = py[i];
                    acc2[2*i]   = add2(add2(a.x, b.x), bkp2[2*i]);
                    acc2[2*i+1] = add2(add2(a.y, b.y), bkp2[2*i+1]);
                }
            }
            #pragma unroll 4
            for (int p = 0; p < 64; p++) {
                float h1 = fmaxf(0.f, fmaf(kw1s[p*3], r0, fmaf(kw1s[p*3+1], r1,
                                fmaf(kw1s[p*3+2], r2, kb1s[p]))));
                u64 hh = dup2(h1);
                const ulonglong2* wv4 = (const ulonglong2*)(WkpT + p*32);
                #pragma unroll
                for (int i = 0; i < 8; i++) {
                    ulonglong2 wv = wv4[i];
                    acc2[2*i]   = fma2(hh, wv.x, acc2[2*i]);
                    acc2[2*i+1] = fma2(hh, wv.y, acc2[2*i+1]);
                }
            }
            {
                ulonglong2* kd = (ulonglong2*)(ks + t*36);
                #pragma unroll
                for (int i = 0; i < 8; i++) kd[i] = make_ulonglong2(acc2[2*i], acc2[2*i+1]);
            }
            {   // v row
                const ulonglong2* px = (const ulonglong2*)(d_gx  + t*E_ + h*HD_);
                const ulonglong2* py = (const ulonglong2*)(d_ngy + m*E_ + h*HD_);
                #pragma unroll
                for (int i = 0; i < 8; i++) {
                    ulonglong2 a = px[i], b = py[i];
                    acc2[2*i]   = add2(add2(a.x, b.x), bkg2[2*i]);
                    acc2[2*i+1] = add2(add2(a.y, b.y), bkg2[2*i+1]);
                }
            }
            #pragma unroll 4
            for (int p = 0; p < 64; p++) {
                float h1 = fmaxf(0.f, fmaf(kw1s[p*3], r0, fmaf(kw1s[p*3+1], r1,
                                fmaf(kw1s[p*3+2], r2, kb1s[p]))));
                u64 hh = dup2(h1);
                const ulonglong2* wv4 = (const ulonglong2*)(WkgT + p*32);
                #pragma unroll
                for (int i = 0; i < 8; i++) {
                    ulonglong2 wv = wv4[i];
                    acc2[2*i]   = fma2(hh, wv.x, acc2[2*i]);
                    acc2[2*i+1] = fma2(hh, wv.y, acc2[2*i+1]);
                }
            }
            {
                ulonglong2* vd = (ulonglong2*)(vs + t*36);
                #pragma unroll
                for (int i = 0; i < 8; i++) vd[i] = make_ulonglong2(acc2[2*i], acc2[2*i+1]);
            }
        }
        __syncthreads();

        // ---- online-softmax attention over this 256-key tile ----
        #pragma unroll 1
        for (int kb = 0; kb < 256; kb += 8) {
            float sA[8], sB[8];
            #pragma unroll 2
            for (int k8 = 0; k8 < 8; k8++) {
                const ulonglong2* kk = (const ulonglong2*)(ks + (kb + k8)*36 + hoff);
                u64 a0 = 0ULL, a1 = 0ULL, b0 = 0ULL, b1 = 0ULL;
                #pragma unroll
                for (int i = 0; i < 4; i++) {
                    ulonglong2 kv = kk[i];
                    a0 = fma2(qA[2*i],   kv.x, a0);
                    a1 = fma2(qA[2*i+1], kv.y, a1);
                    b0 = fma2(qB[2*i],   kv.x, b0);
                    b1 = fma2(qB[2*i+1], kv.y, b1);
                }
                float l0, h0, l1, h1;
                unpack2(a0, l0, h0); unpack2(a1, l1, h1);
                sA[k8] = (l0 + h0) + (l1 + h1);
                unpack2(b0, l0, h0); unpack2(b1, l1, h1);
                sB[k8] = (l0 + h0) + (l1 + h1);
            }
            // complete dot products across the half-dim partner lane
            #pragma unroll
            for (int k8 = 0; k8 < 8; k8++) {
                sA[k8] += __shfl_xor_sync(0xffffffffu, sA[k8], 16);
                sB[k8] += __shfl_xor_sync(0xffffffffu, sB[k8], 16);
            }
            float mnA = mrA, mnB = mrB;
            #pragma unroll
            for (int k8 = 0; k8 < 8; k8++) { mnA = fmaxf(mnA, sA[k8]); mnB = fmaxf(mnB, sB[k8]); }
            float scA = __expf(mrA - mnA), scB = __expf(mrB - mnB);
            float lsA = 0.f, lsB = 0.f;
            #pragma unroll
            for (int k8 = 0; k8 < 8; k8++) {
                sA[k8] = __expf(sA[k8] - mnA); lsA += sA[k8];
                sB[k8] = __expf(sB[k8] - mnB); lsB += sB[k8];
            }
            lrA = fmaf(lrA, scA, lsA); mrA = mnA;
            lrB = fmaf(lrB, scB, lsB); mrB = mnB;
            u64 s2A = dup2(scA), s2B = dup2(scB);
            #pragma unroll
            for (int i = 0; i < 8; i++) { oA[i] = mul2(oA[i], s2A); oB[i] = mul2(oB[i], s2B); }
            #pragma unroll 2
            for (int k8 = 0; k8 < 8; k8++) {
                const ulonglong2* vv = (const ulonglong2*)(vs + (kb + k8)*36 + hoff);
                u64 pA = dup2(sA[k8]), pB = dup2(sB[k8]);
                #pragma unroll
                for (int i = 0; i < 4; i++) {
                    ulonglong2 v = vv[i];
                    oA[2*i]   = fma2(pA, v.x, oA[2*i]);
                    oA[2*i+1] = fma2(pA, v.y, oA[2*i+1]);
                    oB[2*i]   = fma2(pB, v.x, oB[2*i]);
                    oB[2*i+1] = fma2(pB, v.y, oB[2*i+1]);
                }
            }
        }
        __syncthreads();
    }

    int baseA = (h*CH_ + c)*N_ + qAi;
    int baseB = (h*CH_ + c)*N_ + qBi;
    if (half == 0) {
        d_pm[baseA] = mrA; d_pl[baseA] = lrA;
        d_pm[baseB] = mrB; d_pl[baseB] = lrB;
    }
    ulonglong2* opA = (ulonglong2*)(d_po + (size_t)baseA*32 + hoff);
    ulonglong2* opB = (ulonglong2*)(d_po + (size_t)baseB*32 + hoff);
    #pragma unroll
    for (int i = 0; i < 4; i++) {
        opA[i] = make_ulonglong2(oA[2*i], oA[2*i+1]);
        opB[i] = make_ulonglong2(oB[2*i], oB[2*i+1]);
    }
}

// ---------------- C: combine + out-proj + residual + layernorm -----------
__global__ void kfinal(const float* __restrict__ x, const float* __restrict__ out_w,
                       const float* __restrict__ ln_g, const float* __restrict__ ln_b,
                       float* __restrict__ out) {
    int n = blockIdx.x, t = threadIdx.x;   // 256 threads
    __shared__ float so[128];
    __shared__ float red[256], red2[256];
    if (t < 128) {
        int h = t >> 5, d = t & 31;
        float Mx = -INFINITY;
        #pragma unroll 2
        for (int c = 0; c < CH_; c++)
            Mx = fmaxf(Mx, d_pm[(h*CH_ + c)*N_ + n]);
        float L = 0.f, oa = 0.f;
        #pragma unroll 2
        for (int c = 0; c < CH_; c++) {
            int b = (h*CH_ + c)*N_ + n;
            float e = __expf(d_pm[b] - Mx);
            L  = fmaf(d_pl[b], e, L);
            oa = fmaf(d_po[(size_t)b*32 + d], e, oa);
        }
        so[t] = oa / L;
    }
    __syncthreads();
    float r = x[n*256 + t];
    const float* wr = out_w + t*128;
    #pragma unroll 8
    for (int e = 0; e < 128; e++) r = fmaf(so[e], wr[e], r);
    red[t] = r; red2[t] = r*r;
    __syncthreads();
    for (int s = 128; s > 0; s >>= 1) {
        if (t < s) { red[t] += red[t + s]; red2[t] += red2[t + s]; }
        __syncthreads();
    }
    float mu  = red[0] * (1.f/256.f);
    float var = red2[0] * (1.f/256.f) - mu*mu;
    float inv = rsqrtf(var + 1e-5f);
    out[n*256 + t] = (r - mu) * inv * ln_g[t] + ln_b[t];
}

// ---------------- launch --------------------------------------------------
extern "C" void kernel_launch(void* const* d_in, const int* in_sizes, int n_in,
                              void* d_out, int out_size) {
    const float* x       = (const float*)d_in[0];
    const float* y       = (const float*)d_in[1];
    const float* x_pos   = (const float*)d_in[2];
    const float* y_pos   = (const float*)d_in[3];
    const float* theta_w = (const float*)d_in[4];
    const float* phi_w   = (const float*)d_in[5];
    const float* g_w     = (const float*)d_in[6];
    const float* q_w1    = (const float*)d_in[7];
    const float* q_b1    = (const float*)d_in[8];
    const float* q_w2    = (const float*)d_in[9];
    const float* q_b2    = (const float*)d_in[10];
    const float* k_w1    = (const float*)d_in[11];
    const float* k_b1    = (const float*)d_in[12];
    const float* k_w2    = (const float*)d_in[13];
    const float* k_b2    = (const float*)d_in[14];
    const float* out_w   = (const float*)d_in[15];
    const float* ln_g    = (const float*)d_in[16];
    const float* ln_b    = (const float*)d_in[17];
    float* out = (float*)d_out;

    cudaFuncSetAttribute(kattn, cudaFuncAttributeMaxDynamicSharedMemorySize, 91392);

    kfold<<<128, 128>>>(phi_w, g_w, k_w2, k_b2);
    kqpe<<<8, 256>>>(x_pos, q_w1, q_b1, q_w2, q_b2);
    kgemm<<<40, 256>>>(x, y, theta_w, phi_w, g_w);
    kattn<<<296, 256, 91392>>>(x_pos, y_pos, k_w1, k_b1);
    kfinal<<<256, 256>>>(x, out_w, ln_g, ln_b, out);
}

// round 15
// speedup vs baseline: 2.2488x; 2.2488x over previous
#include <cuda_runtime.h>
#include <cuda_bf16.h>
#include <stdint.h>
#include <math.h>

#define N_  256
#define M_  256
#define D_  256
#define E_  128
#define H_  4
#define HD_ 32
#define P_  64
#define CH_ 74    // key chunks per head (variable 3-4 tiles each)

typedef unsigned long long u64;

// ---------------- packed fp32x2 helpers -----------------------------------
__device__ __forceinline__ u64 pack2(float a, float b) {
    u64 r; asm("mov.b64 %0, {%1, %2};" : "=l"(r) : "f"(a), "f"(b)); return r;
}
__device__ __forceinline__ u64 dup2(float a) {
    u64 r; asm("mov.b64 %0, {%1, %1};" : "=l"(r) : "f"(a)); return r;
}
__device__ __forceinline__ void unpack2(u64 v, float& lo, float& hi) {
    asm("mov.b64 {%0, %1}, %2;" : "=f"(lo), "=f"(hi) : "l"(v));
}
__device__ __forceinline__ u64 fma2(u64 a, u64 b, u64 c) {
    u64 d; asm("fma.rn.f32x2 %0, %1, %2, %3;" : "=l"(d) : "l"(a), "l"(b), "l"(c)); return d;
}
__device__ __forceinline__ u64 add2(u64 a, u64 b) {
    u64 d; asm("add.rn.f32x2 %0, %1, %2;" : "=l"(d) : "l"(a), "l"(b)); return d;
}

// ---------------- tensor-core helpers (bf16 m16n8k16) ---------------------
__device__ __forceinline__ uint32_t s2u(const void* p) {
    return (uint32_t)__cvta_generic_to_shared(p);
}
__device__ __forceinline__ void ldsm4(uint32_t& r0, uint32_t& r1, uint32_t& r2, uint32_t& r3, uint32_t a) {
    asm volatile("ldmatrix.sync.aligned.m8n8.x4.shared.b16 {%0,%1,%2,%3}, [%4];"
        : "=r"(r0), "=r"(r1), "=r"(r2), "=r"(r3) : "r"(a));
}
__device__ __forceinline__ void ldsm4t(uint32_t& r0, uint32_t& r1, uint32_t& r2, uint32_t& r3, uint32_t a) {
    asm volatile("ldmatrix.sync.aligned.m8n8.x4.trans.shared.b16 {%0,%1,%2,%3}, [%4];"
        : "=r"(r0), "=r"(r1), "=r"(r2), "=r"(r3) : "r"(a));
}
__device__ __forceinline__ void mma16816(float* c, const uint32_t* a, uint32_t b0, uint32_t b1) {
    asm volatile("mma.sync.aligned.m16n8k16.row.col.f32.bf16.bf16.f32 "
        "{%0,%1,%2,%3}, {%4,%5,%6,%7}, {%8,%9}, {%0,%1,%2,%3};"
        : "+f"(c[0]), "+f"(c[1]), "+f"(c[2]), "+f"(c[3])
        : "r"(a[0]), "r"(a[1]), "r"(a[2]), "r"(a[3]), "r"(b0), "r"(b1));
}
__device__ __forceinline__ uint32_t cvt2bf(float lo, float hi) {
    uint32_t r; asm("cvt.rn.bf16x2.f32 %0, %1, %2;" : "=r"(r) : "f"(hi), "f"(lo)); return r;
}

// ---------------- device scratch (static, no allocations) ----------------
__device__ float d_qpe[N_*E_];
__device__ float d_q[N_*E_];
__device__ float d_phix[N_*E_], d_nphiy[M_*E_];
__device__ float d_gx[N_*E_],  d_ngy[M_*E_];
__device__ float d_Wkp[E_*P_], d_Wkg[E_*P_];
__device__ float d_bkp[E_],    d_bkg[E_];
__device__ float d_pm[H_*CH_*N_], d_pl[H_*CH_*N_];
__device__ float d_po[H_*CH_*N_*HD_];

__device__ __forceinline__ void chunk_range(int c, int& t0, int& t1) {
    if (c < 34) { t0 = 4*c;            t1 = t0 + 4; }
    else        { t0 = 136 + 3*(c-34); t1 = t0 + 3; }
}

// ---------------- A0: fold phi_w[:,D:] @ k_w2 -> Wkp / Wkg ---------------
__global__ void kfold(const float* __restrict__ phi_w, const float* __restrict__ g_w,
                      const float* __restrict__ k_w2, const float* __restrict__ k_b2) {
    int e = blockIdx.x, t = threadIdx.x;
    if (t < 64) {
        float a = 0.f;
        for (int ep = 0; ep < 128; ep++)
            a = fmaf(phi_w[e*384 + 256 + ep], k_w2[ep*64 + t], a);
        d_Wkp[e*64 + t] = a;
    } else {
        int p = t - 64; float a = 0.f;
        for (int ep = 0; ep < 128; ep++)
            a = fmaf(g_w[e*384 + 256 + ep], k_w2[ep*64 + p], a);
        d_Wkg[e*64 + p] = a;
    }
    if (t == 0) {
        float a = 0.f;
        for (int ep = 0; ep < 128; ep++) a = fmaf(phi_w[e*384 + 256 + ep], k_b2[ep], a);
        d_bkp[e] = a;
    }
    if (t == 64) {
        float a = 0.f;
        for (int ep = 0; ep < 128; ep++) a = fmaf(g_w[e*384 + 256 + ep], k_b2[ep], a);
        d_bkg[e] = a;
    }
}

// ---------------- A1: query pos-MLP embedding ----------------------------
__global__ void __launch_bounds__(256)
kqpe(const float* __restrict__ x_pos,
     const float* __restrict__ q_w1, const float* __restrict__ q_b1,
     const float* __restrict__ q_w2, const float* __restrict__ q_b2) {
    __shared__ float sW[128*65];
    __shared__ float hq[32*65];
    __shared__ float w1s[192], b1s[64], b2s[128];
    int t = threadIdx.x, n0 = blockIdx.x * 32;

    for (int i = t; i < 8192; i += 256) {
        int e = i >> 6, p = i & 63;
        sW[e*65 + p] = q_w2[i];
    }
    if (t < 192) w1s[t] = q_w1[t];
    if (t < 64)  b1s[t] = q_b1[t];
    if (t < 128) b2s[t] = q_b2[t];
    __syncthreads();

    for (int i = t; i < 2048; i += 256) {
        int n = i >> 6, p = i & 63;
        float xp0 = x_pos[(n0+n)*3], xp1 = x_pos[(n0+n)*3+1], xp2 = x_pos[(n0+n)*3+2];
        hq[n*65 + p] = fmaxf(0.f, fmaf(w1s[p*3], xp0, fmaf(w1s[p*3+1], xp1,
                              fmaf(w1s[p*3+2], xp2, b1s[p]))));
    }
    __syncthreads();

    int ce = t & 31, rg = t >> 5;
    float acc[4][4];
    #pragma unroll
    for (int i = 0; i < 4; i++)
        #pragma unroll
        for (int j = 0; j < 4; j++) acc[i][j] = b2s[ce + 32*j];
    for (int p = 0; p < 64; p++) {
        float w0 = sW[(ce     )*65 + p], w1 = sW[(ce+32)*65 + p];
        float w2 = sW[(ce+64)*65 + p],  w3 = sW[(ce+96)*65 + p];
        #pragma unroll
        for (int i = 0; i < 4; i++) {
            float xv = hq[(rg*4 + i)*65 + p];
            acc[i][0] = fmaf(xv, w0, acc[i][0]);
            acc[i][1] = fmaf(xv, w1, acc[i][1]);
            acc[i][2] = fmaf(xv, w2, acc[i][2]);
            acc[i][3] = fmaf(xv, w3, acc[i][3]);
        }
    }
    #pragma unroll
    for (int i = 0; i < 4; i++)
        #pragma unroll
        for (int j = 0; j < 4; j++)
            d_qpe[(n0 + rg*4 + i)*128 + ce + 32*j] = acc[i][j];
}

// ---------------- A2: tiled GEMM for q / phix / nphiy / gx / ngy ---------
__global__ void __launch_bounds__(256)
kgemm(const float* __restrict__ x, const float* __restrict__ y,
      const float* __restrict__ theta_w, const float* __restrict__ phi_w,
      const float* __restrict__ g_w) {
    __shared__ float ws[128*65];
    __shared__ float xs[32*65];
    int t = threadIdx.x;
    int job = blockIdx.x >> 3, rt = blockIdx.x & 7;
    int n0 = rt * 32;

    const float* W   = (job == 0) ? theta_w : (job <= 2 ? phi_w : g_w);
    const float* src = (job == 2 || job == 4) ? y : x;
    int   K    = (job == 0) ? 384 : 256;
    float mult = (job == 0) ? 0.17677669529663687f
               : (job == 2 || job == 4) ? -1.f : 1.f;
    float* out = (job == 0) ? d_q : (job == 1) ? d_phix : (job == 2) ? d_nphiy
               : (job == 3) ? d_gx : d_ngy;

    int ce = t & 31, rg = t >> 5;
    float acc[4][4];
    #pragma unroll
    for (int i = 0; i < 4; i++)
        #pragma unroll
        for (int j = 0; j < 4; j++) acc[i][j] = 0.f;

    for (int k0 = 0; k0 < K; k0 += 64) {
        for (int i = t; i < 8192; i += 256) {
            int e = i >> 6, k = i & 63;
            ws[e*65 + k] = W[e*384 + k0 + k];
        }
        for (int i = t; i < 2048; i += 256) {
            int n = i >> 6, k = i & 63;
            float v;
            if (job == 0 && k0 >= 256) v = d_qpe[(n0+n)*128 + (k0 - 256) + k];
            else                       v = src[(n0+n)*256 + k0 + k];
            xs[n*65 + k] = v;
        }
        __syncthreads();
        #pragma unroll 4
        for (int k = 0; k < 64; k++) {
            float w0 = ws[(ce     )*65 + k], w1 = ws[(ce+32)*65 + k];
            float w2 = ws[(ce+64)*65 + k],  w3 = ws[(ce+96)*65 + k];
            #pragma unroll
            for (int i = 0; i < 4; i++) {
                float xv = xs[(rg*4 + i)*65 + k];
                acc[i][0] = fmaf(xv, w0, acc[i][0]);
                acc[i][1] = fmaf(xv, w1, acc[i][1]);
                acc[i][2] = fmaf(xv, w2, acc[i][2]);
                acc[i][3] = fmaf(xv, w3, acc[i][3]);
            }
        }
        __syncthreads();
    }
    #pragma unroll
    for (int i = 0; i < 4; i++)
        #pragma unroll
        for (int j = 0; j < 4; j++)
            out[(n0 + rg*4 + i)*128 + ce + 32*j] = acc[i][j] * mult;
}

// ---------------- B: kv-gen (scalar f32x2) + FA2 attention (bf16 mma) ----
// 256 threads. Warp w owns queries w*32..w*32+31 in mma fragments.
// Thread t generates key/value row t of each tile into bf16 smem.
// smem byte layout (dynamic):
//   kb  bf16[256][40]  @ 0      (20480)   rows stride 80B
//   vb  bf16[256][40]  @ 20480  (20480)
//   WkpT f32[64][32]   @ 40960  (8192)
//   WkgT f32[64][32]   @ 49152  (8192)
//   kw1s f32[192]      @ 57344
//   kb1s f32[64]       @ 58112
//   bkp2 u64[16]       @ 58368
//   bkg2 u64[16]       @ 58496   total 58624
#define OFF_VB  20480
#define OFF_WKP 40960
#define OFF_WKG 49152
#define OFF_KW1 57344
#define OFF_KB1 58112
#define OFF_BKP 58368
#define OFF_BKG 58496
#define SM_TOT  58624

__global__ void __launch_bounds__(256, 2)
kattn(const float* __restrict__ x_pos, const float* __restrict__ y_pos,
      const float* __restrict__ k_w1, const float* __restrict__ k_b1) {
    extern __shared__ char smb[];
    float* WkpT = (float*)(smb + OFF_WKP);
    float* WkgT = (float*)(smb + OFF_WKG);
    float* kw1s = (float*)(smb + OFF_KW1);
    float* kb1s = (float*)(smb + OFF_KB1);
    u64*   bkp2 = (u64*)(smb + OFF_BKP);
    u64*   bkg2 = (u64*)(smb + OFF_BKG);
    uint32_t sbase = s2u(smb);

    int bid = blockIdx.x, t = threadIdx.x;
    int c, h;
    if (bid < 136) { c = bid % 34; h = bid / 34; }
    else {
        int u = bid - 136;
        c = 34 + (u % 40); h = u / 40;
    }
    int t0, t1; chunk_range(c, t0, t1);

    for (int i = t; i < 2048; i += 256) {
        int p = i >> 5, d = i & 31;
        WkpT[i] = d_Wkp[(h*32 + d)*64 + p];
        WkgT[i] = d_Wkg[(h*32 + d)*64 + p];
    }
    for (int i = t; i < 192; i += 256) kw1s[i] = k_w1[i];
    if (t < 64) kb1s[t] = k_b1[t];
    if (t < 16) bkp2[t] = pack2(d_bkp[h*32 + 2*t], d_bkp[h*32 + 2*t + 1]);
    else if (t < 32) { int j = t - 16; bkg2[j] = pack2(d_bkg[h*32 + 2*j], d_bkg[h*32 + 2*j + 1]); }

    // ---- stage Q (bf16) into kb region, load fragments, then release ----
    {
        const float4* qp = (const float4*)(d_q + t*E_ + h*HD_);
        uint32_t wbuf[16];
        #pragma unroll
        for (int i = 0; i < 8; i++) {
            float4 v = qp[i];
            wbuf[2*i]   = cvt2bf(v.x, v.y);
            wbuf[2*i+1] = cvt2bf(v.z, v.w);
        }
        uint4* dst = (uint4*)(smb + t*80);
        #pragma unroll
        for (int i = 0; i < 4; i++)
            dst[i] = make_uint4(wbuf[4*i], wbuf[4*i+1], wbuf[4*i+2], wbuf[4*i+3]);
    }
    __syncthreads();

    int l = t & 31, w = t >> 5;
    uint32_t qf[2][2][4];   // [mtile][kstep(d)][frag]
    #pragma unroll
    for (int i = 0; i < 2; i++) {
        int qrow = w*32 + 16*i + (l & 7) + ((l >> 3) & 1) * 8;
        uint32_t col = ((l >> 4) & 1) * 16;
        ldsm4(qf[i][0][0], qf[i][0][1], qf[i][0][2], qf[i][0][3], sbase + qrow*80 + col);
        ldsm4(qf[i][1][0], qf[i][1][1], qf[i][1][2], qf[i][1][3], sbase + qrow*80 + col + 32);
    }
    __syncthreads();

    float of[2][4][4];      // O accum [mtile][dimtile][frag]
    #pragma unroll
    for (int i = 0; i < 2; i++)
        #pragma unroll
        for (int j = 0; j < 4; j++)
            #pragma unroll
            for (int k = 0; k < 4; k++) of[i][j][k] = 0.f;
    float mst[2][2], lst[2][2];
    #pragma unroll
    for (int i = 0; i < 2; i++)
        #pragma unroll
        for (int hh = 0; hh < 2; hh++) { mst[i][hh] = -INFINITY; lst[i][hh] = 0.f; }

    float xp0 = x_pos[t*3], xp1 = x_pos[t*3+1], xp2 = x_pos[t*3+2];

    for (int m = t0; m < t1; ++m) {
        float r0 = xp0 - y_pos[m*3];
        float r1 = xp1 - y_pos[m*3+1];
        float r2 = xp2 - y_pos[m*3+2];

        // ---- K row t (fp32 gen -> bf16 store) ----
        {
            u64 acc2[16];
            const ulonglong2* px = (const ulonglong2*)(d_phix  + t*E_ + h*HD_);
            const ulonglong2* py = (const ulonglong2*)(d_nphiy + m*E_ + h*HD_);
            #pragma unroll
            for (int i = 0; i < 8; i++) {
                ulonglong2 a = px[i], b = py[i];
                acc2[2*i]   = add2(add2(a.x, b.x), bkp2[2*i]);
                acc2[2*i+1] = add2(add2(a.y, b.y), bkp2[2*i+1]);
            }
            #pragma unroll 4
            for (int p = 0; p < 64; p++) {
                float h1 = fmaxf(0.f, fmaf(kw1s[p*3], r0, fmaf(kw1s[p*3+1], r1,
                                fmaf(kw1s[p*3+2], r2, kb1s[p]))));
                u64 hh = dup2(h1);
                const ulonglong2* wv4 = (const ulonglong2*)(WkpT + p*32);
                #pragma unroll
                for (int i = 0; i < 8; i++) {
                    ulonglong2 wv = wv4[i];
                    acc2[2*i]   = fma2(hh, wv.x, acc2[2*i]);
                    acc2[2*i+1] = fma2(hh, wv.y, acc2[2*i+1]);
                }
            }
            uint32_t wbuf[16];
            #pragma unroll
            for (int i = 0; i < 16; i++) {
                float lo, hi; unpack2(acc2[i], lo, hi);
                wbuf[i] = cvt2bf(lo, hi);
            }
            uint4* kd = (uint4*)(smb + t*80);
            #pragma unroll
            for (int i = 0; i < 4; i++)
                kd[i] = make_uint4(wbuf[4*i], wbuf[4*i+1], wbuf[4*i+2], wbuf[4*i+3]);
        }
        // ---- V row t ----
        {
            u64 acc2[16];
            const ulonglong2* px = (const ulonglong2*)(d_gx  + t*E_ + h*HD_);
            const ulonglong2* py = (const ulonglong2*)(d_ngy + m*E_ + h*HD_);
            #pragma unroll
            for (int i = 0; i < 8; i++) {
                ulonglong2 a = px[i], b = py[i];
                acc2[2*i]   = add2(add2(a.x, b.x), bkg2[2*i]);
                acc2[2*i+1] = add2(add2(a.y, b.y), bkg2[2*i+1]);
            }
            #pragma unroll 4
            for (int p = 0; p < 64; p++) {
                float h1 = fmaxf(0.f, fmaf(kw1s[p*3], r0, fmaf(kw1s[p*3+1], r1,
                                fmaf(kw1s[p*3+2], r2, kb1s[p]))));
                u64 hh = dup2(h1);
                const ulonglong2* wv4 = (const ulonglong2*)(WkgT + p*32);
                #pragma unroll
                for (int i = 0; i < 8; i++) {
                    ulonglong2 wv = wv4[i];
                    acc2[2*i]   = fma2(hh, wv.x, acc2[2*i]);
                    acc2[2*i+1] = fma2(hh, wv.y, acc2[2*i+1]);
                }
            }
            uint32_t wbuf[16];
            #pragma unroll
            for (int i = 0; i < 16; i++) {
                float lo, hi; unpack2(acc2[i], lo, hi);
                wbuf[i] = cvt2bf(lo, hi);
            }
            uint4* vd = (uint4*)(smb + OFF_VB + t*80);
            #pragma unroll
            for (int i = 0; i < 4; i++)
                vd[i] = make_uint4(wbuf[4*i], wbuf[4*i+1], wbuf[4*i+2], wbuf[4*i+3]);
        }
        __syncthreads();

        // ---- attention over this 256-key tile, 32-key blocks ----
        #pragma unroll 1
        for (int kb0 = 0; kb0 < 256; kb0 += 32) {
            float sf[2][4][4];
            #pragma unroll
            for (int i = 0; i < 2; i++)
                #pragma unroll
                for (int j = 0; j < 4; j++)
                    #pragma unroll
                    for (int k = 0; k < 4; k++) sf[i][j][k] = 0.f;

            // QK: per 8-key n-tile, one ldsm4 covers all 32 dims
            #pragma unroll
            for (int j = 0; j < 4; j++) {
                uint32_t b0, b1, b2, b3;
                int krow = kb0 + 8*j + (l & 7);
                ldsm4(b0, b1, b2, b3, sbase + krow*80 + (l >> 3)*16);
                #pragma unroll
                for (int i = 0; i < 2; i++) {
                    mma16816(sf[i][j], qf[i][0], b0, b1);
                    mma16816(sf[i][j], qf[i][1], b2, b3);
                }
            }

            // online softmax (per row-slot; 4 shfl each, per 32-key block)
            #pragma unroll
            for (int i = 0; i < 2; i++)
                #pragma unroll
                for (int hh = 0; hh < 2; hh++) {
                    float bm = sf[i][0][2*hh];
                    #pragma unroll
                    for (int j = 0; j < 4; j++) {
                        bm = fmaxf(bm, sf[i][j][2*hh]);
                        bm = fmaxf(bm, sf[i][j][2*hh+1]);
                    }
                    bm = fmaxf(bm, __shfl_xor_sync(0xffffffffu, bm, 1));
                    bm = fmaxf(bm, __shfl_xor_sync(0xffffffffu, bm, 2));
                    float mn = fmaxf(mst[i][hh], bm);
                    float sc = __expf(mst[i][hh] - mn);
                    mst[i][hh] = mn;
                    float ps = 0.f;
                    #pragma unroll
                    for (int j = 0; j < 4; j++) {
                        float p0 = __expf(sf[i][j][2*hh]   - mn);
                        float p1 = __expf(sf[i][j][2*hh+1] - mn);
                        sf[i][j][2*hh] = p0; sf[i][j][2*hh+1] = p1;
                        ps += p0 + p1;
                    }
                    ps += __shfl_xor_sync(0xffffffffu, ps, 1);
                    ps += __shfl_xor_sync(0xffffffffu, ps, 2);
                    lst[i][hh] = lst[i][hh]*sc + ps;
                    #pragma unroll
                    for (int j = 0; j < 4; j++) {
                        of[i][j][2*hh]   *= sc;
                        of[i][j][2*hh+1] *= sc;
                    }
                }

            // PV: 2 k-steps of 16 keys
            #pragma unroll
            for (int u = 0; u < 2; u++) {
                uint32_t c0, c1, c2, c3, e0, e1, e2, e3;
                int kr = kb0 + 16*u + (l & 7);
                ldsm4t(c0, c1, c2, c3, sbase + OFF_VB + kr*80     + (l >> 3)*16);
                ldsm4t(e0, e1, e2, e3, sbase + OFF_VB + (kr+8)*80 + (l >> 3)*16);
                #pragma unroll
                for (int i = 0; i < 2; i++) {
                    uint32_t pa[4];
                    pa[0] = cvt2bf(sf[i][2*u][0],   sf[i][2*u][1]);
                    pa[1] = cvt2bf(sf[i][2*u][2],   sf[i][2*u][3]);
                    pa[2] = cvt2bf(sf[i][2*u+1][0], sf[i][2*u+1][1]);
                    pa[3] = cvt2bf(sf[i][2*u+1][2], sf[i][2*u+1][3]);
                    mma16816(of[i][0], pa, c0, e0);
                    mma16816(of[i][1], pa, c1, e1);
                    mma16816(of[i][2], pa, c2, e2);
                    mma16816(of[i][3], pa, c3, e3);
                }
            }
        }
        __syncthreads();
    }

    // ---- epilogue: write partial softmax stats + unnormalized O ----
    #pragma unroll
    for (int i = 0; i < 2; i++)
        #pragma unroll
        for (int hh = 0; hh < 2; hh++) {
            int qrow = w*32 + 16*i + (l >> 2) + 8*hh;
            int base = (h*CH_ + c)*N_ + qrow;
            if ((l & 3) == 0) {
                d_pm[base] = mst[i][hh];
                d_pl[base] = lst[i][hh];
            }
            float* op = d_po + (size_t)base*32 + 2*(l & 3);
            #pragma unroll
            for (int j = 0; j < 4; j++) {
                float2 v = make_float2(of[i][j][2*hh], of[i][j][2*hh+1]);
                *(float2*)(op + 8*j) = v;
            }
        }
}

// ---------------- C: combine + out-proj + residual + layernorm -----------
__global__ void kfinal(const float* __restrict__ x, const float* __restrict__ out_w,
                       const float* __restrict__ ln_g, const float* __restrict__ ln_b,
                       float* __restrict__ out) {
    int n = blockIdx.x, t = threadIdx.x;   // 256 threads
    __shared__ float so[128];
    __shared__ float red[256], red2[256];
    if (t < 128) {
        int h = t >> 5, d = t & 31;
        float Mx = -INFINITY;
        #pragma unroll 2
        for (int c = 0; c < CH_; c++)
            Mx = fmaxf(Mx, d_pm[(h*CH_ + c)*N_ + n]);
        float L = 0.f, oa = 0.f;
        #pragma unroll 2
        for (int c = 0; c < CH_; c++) {
            int b = (h*CH_ + c)*N_ + n;
            float e = __expf(d_pm[b] - Mx);
            L  = fmaf(d_pl[b], e, L);
            oa = fmaf(d_po[(size_t)b*32 + d], e, oa);
        }
        so[t] = oa / L;
    }
    __syncthreads();
    float r = x[n*256 + t];
    const float* wr = out_w + t*128;
    #pragma unroll 8
    for (int e = 0; e < 128; e++) r = fmaf(so[e], wr[e], r);
    red[t] = r; red2[t] = r*r;
    __syncthreads();
    for (int s = 128; s > 0; s >>= 1) {
        if (t < s) { red[t] += red[t + s]; red2[t] += red2[t + s]; }
        __syncthreads();
    }
    float mu  = red[0] * (1.f/256.f);
    float var = red2[0] * (1.f/256.f) - mu*mu;
    float inv = rsqrtf(var + 1e-5f);
    out[n*256 + t] = (r - mu) * inv * ln_g[t] + ln_b[t];
}

// ---------------- launch --------------------------------------------------
extern "C" void kernel_launch(void* const* d_in, const int* in_sizes, int n_in,
                              void* d_out, int out_size) {
    const float* x       = (const float*)d_in[0];
    const float* y       = (const float*)d_in[1];
    const float* x_pos   = (const float*)d_in[2];
    const float* y_pos   = (const float*)d_in[3];
    const float* theta_w = (const float*)d_in[4];
    const float* phi_w   = (const float*)d_in[5];
    const float* g_w     = (const float*)d_in[6];
    const float* q_w1    = (const float*)d_in[7];
    const float* q_b1    = (const float*)d_in[8];
    const float* q_w2    = (const float*)d_in[9];
    const float* q_b2    = (const float*)d_in[10];
    const float* k_w1    = (const float*)d_in[11];
    const float* k_b1    = (const float*)d_in[12];
    const float* k_w2    = (const float*)d_in[13];
    const float* k_b2    = (const float*)d_in[14];
    const float* out_w   = (const float*)d_in[15];
    const float* ln_g    = (const float*)d_in[16];
    const float* ln_b    = (const float*)d_in[17];
    float* out = (float*)d_out;

    cudaFuncSetAttribute(kattn, cudaFuncAttributeMaxDynamicSharedMemorySize, SM_TOT);

    kfold<<<128, 128>>>(phi_w, g_w, k_w2, k_b2);
    kqpe<<<8, 256>>>(x_pos, q_w1, q_b1, q_w2, q_b2);
    kgemm<<<40, 256>>>(x, y, theta_w, phi_w, g_w);
    kattn<<<296, 256, SM_TOT>>>(x_pos, y_pos, k_w1, k_b1);
    kfinal<<<256, 256>>>(x, out_w, ln_g, ln_b, out);
}

// round 16
// speedup vs baseline: 3.6179x; 1.6089x over previous
#include <cuda_runtime.h>
#include <cuda_bf16.h>
#include <stdint.h>
#include <math.h>

#define N_  256
#define M_  256
#define D_  256
#define E_  128
#define H_  4
#define HD_ 32
#define P_  64
#define CH_ 37    // key chunks per head (34 chunks of 7 tiles + 3 of 6)

typedef unsigned long long u64;

// ---------------- tensor-core helpers (bf16 m16n8k16) ---------------------
__device__ __forceinline__ uint32_t s2u(const void* p) {
    return (uint32_t)__cvta_generic_to_shared(p);
}
__device__ __forceinline__ void ldsm4(uint32_t& r0, uint32_t& r1, uint32_t& r2, uint32_t& r3, uint32_t a) {
    asm volatile("ldmatrix.sync.aligned.m8n8.x4.shared.b16 {%0,%1,%2,%3}, [%4];"
        : "=r"(r0), "=r"(r1), "=r"(r2), "=r"(r3) : "r"(a));
}
__device__ __forceinline__ void ldsm4t(uint32_t& r0, uint32_t& r1, uint32_t& r2, uint32_t& r3, uint32_t a) {
    asm volatile("ldmatrix.sync.aligned.m8n8.x4.trans.shared.b16 {%0,%1,%2,%3}, [%4];"
        : "=r"(r0), "=r"(r1), "=r"(r2), "=r"(r3) : "r"(a));
}
__device__ __forceinline__ void mma16816(float* c, const uint32_t* a, uint32_t b0, uint32_t b1) {
    asm volatile("mma.sync.aligned.m16n8k16.row.col.f32.bf16.bf16.f32 "
        "{%0,%1,%2,%3}, {%4,%5,%6,%7}, {%8,%9}, {%0,%1,%2,%3};"
        : "+f"(c[0]), "+f"(c[1]), "+f"(c[2]), "+f"(c[3])
        : "r"(a[0]), "r"(a[1]), "r"(a[2]), "r"(a[3]), "r"(b0), "r"(b1));
}
__device__ __forceinline__ uint32_t cvt2bf(float lo, float hi) {
    uint32_t r; asm("cvt.rn.bf16x2.f32 %0, %1, %2;" : "=r"(r) : "f"(hi), "f"(lo)); return r;
}
__device__ __forceinline__ float bf_lo(uint32_t p) { return __uint_as_float(p << 16); }
__device__ __forceinline__ float bf_hi(uint32_t p) { return __uint_as_float(p & 0xffff0000u); }

// ---------------- device scratch (static, no allocations) ----------------
__device__ float d_q[N_*E_];
__device__ float d_phix[N_*E_], d_nphiy[M_*E_];    // nphiy/ngy NEGATED
__device__ float d_gx[N_*E_],  d_ngy[M_*E_];
__device__ float d_Wkp[E_*P_], d_Wkg[E_*P_];
__device__ float d_bkp[E_],    d_bkg[E_];
__device__ float d_pm[H_*CH_*N_], d_pl[H_*CH_*N_];
__device__ float d_po[H_*CH_*N_*HD_];

__device__ __forceinline__ void chunk_range(int c, int& t0, int& t1) {
    if (c < 34) { t0 = 7*c;            t1 = t0 + 7; }
    else        { t0 = 238 + 6*(c-34); t1 = t0 + 6; }
}

// ---------------- A: fused prep (gemm with inline qpe + fold) ------------
// grid 168, 256 threads, dynamic smem. blocks [0,40): gemm jobs; [40,168): fold.
// dyn smem float offsets: ws@0 (128*65), xs@8320 (32*65), qpe@10400 (32*130),
//                         w1s@14560(192), b1s@14752(64), b2s@14816(128)
#define PREP_SMF 14944
__global__ void __launch_bounds__(256)
kprep(const float* __restrict__ x, const float* __restrict__ y,
      const float* __restrict__ x_pos,
      const float* __restrict__ theta_w, const float* __restrict__ phi_w,
      const float* __restrict__ g_w,
      const float* __restrict__ q_w1, const float* __restrict__ q_b1,
      const float* __restrict__ q_w2, const float* __restrict__ q_b2,
      const float* __restrict__ k_w2, const float* __restrict__ k_b2) {
    int b = blockIdx.x, t = threadIdx.x;
    if (b >= 40) {                    // -------- fold --------
        int e = b - 40;
        if (t < 64) {
            float a = 0.f;
            for (int ep = 0; ep < 128; ep++)
                a = fmaf(phi_w[e*384 + 256 + ep], k_w2[ep*64 + t], a);
            d_Wkp[e*64 + t] = a;
        } else if (t < 128) {
            int p = t - 64; float a = 0.f;
            for (int ep = 0; ep < 128; ep++)
                a = fmaf(g_w[e*384 + 256 + ep], k_w2[ep*64 + p], a);
            d_Wkg[e*64 + p] = a;
        } else if (t == 128) {
            float a = 0.f;
            for (int ep = 0; ep < 128; ep++) a = fmaf(phi_w[e*384 + 256 + ep], k_b2[ep], a);
            d_bkp[e] = a;
        } else if (t == 129) {
            float a = 0.f;
            for (int ep = 0; ep < 128; ep++) a = fmaf(g_w[e*384 + 256 + ep], k_b2[ep], a);
            d_bkg[e] = a;
        }
        return;
    }
    extern __shared__ float sp[];
    float* ws  = sp;
    float* xs  = sp + 8320;
    float* qpe = sp + 10400;
    float* w1s = sp + 14560;
    float* b1s = sp + 14752;
    float* b2s = sp + 14816;

    int job = b >> 3, rt = b & 7, n0 = rt * 32;
    const float* W   = (job == 0) ? theta_w : (job <= 2 ? phi_w : g_w);
    const float* src = (job == 2 || job == 4) ? y : x;
    int   K    = (job == 0) ? 384 : 256;
    float mult = (job == 0) ? 0.17677669529663687f
               : (job == 2 || job == 4) ? -1.f : 1.f;
    float* out = (job == 0) ? d_q : (job == 1) ? d_phix : (job == 2) ? d_nphiy
               : (job == 3) ? d_gx : d_ngy;

    int ce = t & 31, rg = t >> 5;

    if (job == 0) {                   // inline pos-MLP embedding for rows n0..n0+31
        for (int i = t; i < 8192; i += 256) {       // q_w2 [e][p] into ws
            int e = i >> 6, p = i & 63;
            ws[e*65 + p] = q_w2[i];
        }
        if (t < 192) w1s[t] = q_w1[t];
        if (t < 64)  b1s[t] = q_b1[t];
        if (t < 128) b2s[t] = q_b2[t];
        __syncthreads();
        for (int i = t; i < 2048; i += 256) {       // hidden into xs
            int n = i >> 6, p = i & 63;
            float xp0 = x_pos[(n0+n)*3], xp1 = x_pos[(n0+n)*3+1], xp2 = x_pos[(n0+n)*3+2];
            xs[n*65 + p] = fmaxf(0.f, fmaf(w1s[p*3], xp0, fmaf(w1s[p*3+1], xp1,
                                  fmaf(w1s[p*3+2], xp2, b1s[p]))));
        }
        __syncthreads();
        float acc[4][4];
        #pragma unroll
        for (int i = 0; i < 4; i++)
            #pragma unroll
            for (int j = 0; j < 4; j++) acc[i][j] = b2s[ce + 32*j];
        for (int p = 0; p < 64; p++) {
            float w0 = ws[(ce     )*65 + p], w1 = ws[(ce+32)*65 + p];
            float w2 = ws[(ce+64)*65 + p],  w3 = ws[(ce+96)*65 + p];
            #pragma unroll
            for (int i = 0; i < 4; i++) {
                float xv = xs[(rg*4 + i)*65 + p];
                acc[i][0] = fmaf(xv, w0, acc[i][0]);
                acc[i][1] = fmaf(xv, w1, acc[i][1]);
                acc[i][2] = fmaf(xv, w2, acc[i][2]);
                acc[i][3] = fmaf(xv, w3, acc[i][3]);
            }
        }
        __syncthreads();
        #pragma unroll
        for (int i = 0; i < 4; i++)
            #pragma unroll
            for (int j = 0; j < 4; j++)
                qpe[(rg*4 + i)*130 + ce + 32*j] = acc[i][j];
        __syncthreads();
    }

    float acc[4][4];
    #pragma unroll
    for (int i = 0; i < 4; i++)
        #pragma unroll
        for (int j = 0; j < 4; j++) acc[i][j] = 0.f;

    for (int k0 = 0; k0 < K; k0 += 64) {
        for (int i = t; i < 8192; i += 256) {
            int e = i >> 6, k = i & 63;
            ws[e*65 + k] = W[e*384 + k0 + k];
        }
        for (int i = t; i < 2048; i += 256) {
            int n = i >> 6, k = i & 63;
            float v;
            if (job == 0 && k0 >= 256) v = qpe[n*130 + (k0 - 256) + k];
            else                       v = src[(n0+n)*256 + k0 + k];
            xs[n*65 + k] = v;
        }
        __syncthreads();
        #pragma unroll 4
        for (int k = 0; k < 64; k++) {
            float w0 = ws[(ce     )*65 + k], w1 = ws[(ce+32)*65 + k];
            float w2 = ws[(ce+64)*65 + k],  w3 = ws[(ce+96)*65 + k];
            #pragma unroll
            for (int i = 0; i < 4; i++) {
                float xv = xs[(rg*4 + i)*65 + k];
                acc[i][0] = fmaf(xv, w0, acc[i][0]);
                acc[i][1] = fmaf(xv, w1, acc[i][1]);
                acc[i][2] = fmaf(xv, w2, acc[i][2]);
                acc[i][3] = fmaf(xv, w3, acc[i][3]);
            }
        }
        __syncthreads();
    }
    #pragma unroll
    for (int i = 0; i < 4; i++)
        #pragma unroll
        for (int j = 0; j < 4; j++)
            out[(n0 + rg*4 + i)*128 + ce + 32*j] = acc[i][j] * mult;
}

// ---------------- B: full-mma kattn (512 thr, 148 CTAs, CH=37) -----------
// smem byte layout:
//   K    bf16[256][40] @ 0      (rows stride 80B)
//   V    bf16[256][40] @ 20480
//   H1   bf16[256][72] @ 40960  (rows stride 144B; also Q staging at prologue)
//   WK   bf16[32][72]  @ 77824  (Wkp head slice [dim][p], stride 144B)
//   WV   bf16[32][72]  @ 82432
//   kw1s f32[192]      @ 87040
//   kb1s f32[64]       @ 87808
//   cscK f32[32]       @ 88064
//   cscV f32[32]       @ 88192    total 88320
#define OFF_V   20480
#define OFF_H1  40960
#define OFF_WK  77824
#define OFF_WV  82432
#define OFF_KW1 87040
#define OFF_KB1 87808
#define OFF_CSK 88064
#define OFF_CSV 88192
#define SM_TOT  88320

__global__ void __launch_bounds__(512, 1)
kattn(const float* __restrict__ x_pos, const float* __restrict__ y_pos,
      const float* __restrict__ k_w1, const float* __restrict__ k_b1) {
    extern __shared__ char smb[];
    float* kw1s = (float*)(smb + OFF_KW1);
    float* kb1s = (float*)(smb + OFF_KB1);
    float* cscK = (float*)(smb + OFF_CSK);
    float* cscV = (float*)(smb + OFF_CSV);
    uint32_t sbase = s2u(smb);

    int bid = blockIdx.x, t = threadIdx.x;
    int h = bid / CH_, c = bid % CH_;
    int t0, t1; chunk_range(c, t0, t1);
    int l = t & 31, wv = t >> 5;

    // ---- stage weights bf16 [dim][p] ----
    for (int i = t; i < 1024; i += 512) {         // 32 dims x 32 p-pairs
        int d = i >> 5, pp = i & 31;
        float2 vk = *(const float2*)(d_Wkp + (h*32 + d)*64 + 2*pp);
        float2 vg = *(const float2*)(d_Wkg + (h*32 + d)*64 + 2*pp);
        *(uint32_t*)(smb + OFF_WK + d*144 + pp*4) = cvt2bf(vk.x, vk.y);
        *(uint32_t*)(smb + OFF_WV + d*144 + pp*4) = cvt2bf(vg.x, vg.y);
    }
    for (int i = t; i < 192; i += 512) kw1s[i] = k_w1[i];
    if (t < 64) kb1s[t] = k_b1[t];

    // ---- stage Q bf16 into H1 region (stride 144) ----
    if (t < 256) {
        const float4* qp = (const float4*)(d_q + t*E_ + h*HD_);
        uint32_t wb[16];
        #pragma unroll
        for (int i = 0; i < 8; i++) {
            float4 v = qp[i];
            wb[2*i]   = cvt2bf(v.x, v.y);
            wb[2*i+1] = cvt2bf(v.z, v.w);
        }
        uint4* dst = (uint4*)(smb + OFF_H1 + t*144);
        #pragma unroll
        for (int i = 0; i < 4; i++)
            dst[i] = make_uint4(wb[4*i], wb[4*i+1], wb[4*i+2], wb[4*i+3]);
    }
    __syncthreads();

    // ---- Q fragments (1 mtile of 16 rows per warp) ----
    uint32_t qf[2][4];
    {
        int qrow = wv*16 + (l & 7) + ((l >> 3) & 1) * 8;
        uint32_t col = ((l >> 4) & 1) * 16;
        ldsm4(qf[0][0], qf[0][1], qf[0][2], qf[0][3], sbase + OFF_H1 + qrow*144 + col);
        ldsm4(qf[1][0], qf[1][1], qf[1][2], qf[1][3], sbase + OFF_H1 + qrow*144 + col + 32);
    }
    // ---- phix / gx base fragments (bf16x2 pairs, tile-invariant, 32 regs) ----
    uint32_t phixp[8], gxp[8];
    #pragma unroll
    for (int hh = 0; hh < 2; hh++)
        #pragma unroll
        for (int j = 0; j < 4; j++) {
            int row  = wv*16 + (l >> 2) + 8*hh;
            int colf = h*32 + 2*(l & 3) + 8*j;
            float2 vp = *(const float2*)(d_phix + row*128 + colf);
            float2 vg = *(const float2*)(d_gx   + row*128 + colf);
            phixp[hh*4+j] = cvt2bf(vp.x, vp.y);
            gxp[hh*4+j]   = cvt2bf(vg.x, vg.y);
        }
    __syncthreads();   // Q frags consumed before H1 overwritten

    float of[4][4];
    #pragma unroll
    for (int j = 0; j < 4; j++)
        #pragma unroll
        for (int k = 0; k < 4; k++) of[j][k] = 0.f;
    float mst[2] = {-INFINITY, -INFINITY}, lst[2] = {0.f, 0.f};

    int hrow = t & 255, phalf = t >> 8;
    float xp0 = x_pos[hrow*3], xp1 = x_pos[hrow*3+1], xp2 = x_pos[hrow*3+2];

    #pragma unroll 1
    for (int m = t0; m < t1; ++m) {
        // col scalars: bias - phi_y[m] (nphiy already negated)
        if (t < 32)       cscK[t]    = d_bkp[h*32 + t]      + d_nphiy[m*128 + h*32 + t];
        else if (t < 64)  cscV[t-32] = d_bkg[h*32 + (t-32)] + d_ngy[m*128 + h*32 + (t-32)];

        // ---- h1 gen: row hrow, p-range phalf*32..+31, bf16 to smem ----
        {
            float r0 = xp0 - y_pos[m*3], r1 = xp1 - y_pos[m*3+1], r2 = xp2 - y_pos[m*3+2];
            uint32_t hb[16];
            #pragma unroll
            for (int pp = 0; pp < 16; pp++) {
                int p = phalf*32 + 2*pp;
                float a = fmaxf(0.f, fmaf(kw1s[p*3],     r0, fmaf(kw1s[p*3+1],     r1,
                               fmaf(kw1s[p*3+2],     r2, kb1s[p]))));
                float b = fmaxf(0.f, fmaf(kw1s[p*3+3],   r0, fmaf(kw1s[p*3+4],     r1,
                               fmaf(kw1s[p*3+5],     r2, kb1s[p+1]))));
                hb[pp] = cvt2bf(a, b);
            }
            uint4* hd = (uint4*)(smb + OFF_H1 + hrow*144 + phalf*64);
            #pragma unroll
            for (int i = 0; i < 4; i++)
                hd[i] = make_uint4(hb[4*i], hb[4*i+1], hb[4*i+2], hb[4*i+3]);
        }
        __syncthreads();

        // ---- A frags: h1 rows for this warp's 16 keys (shared K/V) ----
        uint32_t af[4][4];
        {
            int arow = wv*16 + (l & 7) + ((l >> 3) & 1) * 8;
            uint32_t acol = ((l >> 4) & 1) * 16;
            #pragma unroll
            for (int u = 0; u < 4; u++)
                ldsm4(af[u][0], af[u][1], af[u][2], af[u][3],
                      sbase + OFF_H1 + arow*144 + acol + 32*u);
        }
        // ---- K then V generation via mma ----
        #pragma unroll
        for (int pass = 0; pass < 2; pass++) {
            uint32_t woff = pass ? OFF_WV : OFF_WK;
            const float* csc = pass ? cscV : cscK;
            const uint32_t* bfr = pass ? gxp : phixp;
            uint32_t koff = pass ? OFF_V : 0;
            float cf[4][4];
            #pragma unroll
            for (int j = 0; j < 4; j++)
                #pragma unroll
                for (int k = 0; k < 4; k++) cf[j][k] = 0.f;
            #pragma unroll
            for (int j = 0; j < 4; j++) {
                uint32_t b0,b1,b2,b3,b4,b5,b6,b7;
                int wrow = 8*j + (l & 7);
                uint32_t wcol = (l >> 3) * 16;
                ldsm4(b0,b1,b2,b3, sbase + woff + wrow*144 + wcol);
                ldsm4(b4,b5,b6,b7, sbase + woff + wrow*144 + wcol + 64);
                mma16816(cf[j], af[0], b0, b1);
                mma16816(cf[j], af[1], b2, b3);
                mma16816(cf[j], af[2], b4, b5);
                mma16816(cf[j], af[3], b6, b7);
            }
            #pragma unroll
            for (int j = 0; j < 4; j++) {
                float2 cs = *(const float2*)(csc + 2*(l & 3) + 8*j);
                #pragma unroll
                for (int hh = 0; hh < 2; hh++) {
                    uint32_t bp = bfr[hh*4+j];
                    float v0 = cf[j][2*hh]   + bf_lo(bp) + cs.x;
                    float v1 = cf[j][2*hh+1] + bf_hi(bp) + cs.y;
                    int row = wv*16 + (l >> 2) + 8*hh;
                    *(uint32_t*)(smb + koff + row*80 + 4*(l & 3) + 16*j) = cvt2bf(v0, v1);
                }
            }
        }
        __syncthreads();

        // ---- attention over this 256-key tile, 32-key blocks ----
        #pragma unroll 1
        for (int kb0 = 0; kb0 < 256; kb0 += 32) {
            float sf[4][4];
            #pragma unroll
            for (int j = 0; j < 4; j++)
                #pragma unroll
                for (int k = 0; k < 4; k++) sf[j][k] = 0.f;
            #pragma unroll
            for (int j = 0; j < 4; j++) {
                uint32_t b0, b1, b2, b3;
                int krow = kb0 + 8*j + (l & 7);
                ldsm4(b0, b1, b2, b3, sbase + krow*80 + (l >> 3)*16);
                mma16816(sf[j], qf[0], b0, b1);
                mma16816(sf[j], qf[1], b2, b3);
            }
            #pragma unroll
            for (int hh = 0; hh < 2; hh++) {
                float bm = sf[0][2*hh];
                #pragma unroll
                for (int j = 0; j < 4; j++) {
                    bm = fmaxf(bm, sf[j][2*hh]);
                    bm = fmaxf(bm, sf[j][2*hh+1]);
                }
                bm = fmaxf(bm, __shfl_xor_sync(0xffffffffu, bm, 1));
                bm = fmaxf(bm, __shfl_xor_sync(0xffffffffu, bm, 2));
                float mn = fmaxf(mst[hh], bm);
                float sc = __expf(mst[hh] - mn);
                mst[hh] = mn;
                float ps = 0.f;
                #pragma unroll
                for (int j = 0; j < 4; j++) {
                    float p0 = __expf(sf[j][2*hh]   - mn);
                    float p1 = __expf(sf[j][2*hh+1] - mn);
                    sf[j][2*hh] = p0; sf[j][2*hh+1] = p1;
                    ps += p0 + p1;
                }
                ps += __shfl_xor_sync(0xffffffffu, ps, 1);
                ps += __shfl_xor_sync(0xffffffffu, ps, 2);
                lst[hh] = lst[hh]*sc + ps;
                #pragma unroll
                for (int j = 0; j < 4; j++) {
                    of[j][2*hh]   *= sc;
                    of[j][2*hh+1] *= sc;
                }
            }
            #pragma unroll
            for (int u = 0; u < 2; u++) {
                uint32_t c0, c1, c2, c3, e0, e1, e2, e3;
                int kr = kb0 + 16*u + (l & 7);
                ldsm4t(c0, c1, c2, c3, sbase + OFF_V + kr*80     + (l >> 3)*16);
                ldsm4t(e0, e1, e2, e3, sbase + OFF_V + (kr+8)*80 + (l >> 3)*16);
                uint32_t pa[4];
                pa[0] = cvt2bf(sf[2*u][0],   sf[2*u][1]);
                pa[1] = cvt2bf(sf[2*u][2],   sf[2*u][3]);
                pa[2] = cvt2bf(sf[2*u+1][0], sf[2*u+1][1]);
                pa[3] = cvt2bf(sf[2*u+1][2], sf[2*u+1][3]);
                mma16816(of[0], pa, c0, e0);
                mma16816(of[1], pa, c1, e1);
                mma16816(of[2], pa, c2, e2);
                mma16816(of[3], pa, c3, e3);
            }
        }
    }

    // ---- epilogue: partial stats + unnormalized O ----
    #pragma unroll
    for (int hh = 0; hh < 2; hh++) {
        int qrow = wv*16 + (l >> 2) + 8*hh;
        int base = (h*CH_ + c)*N_ + qrow;
        if ((l & 3) == 0) {
            d_pm[base] = mst[hh];
            d_pl[base] = lst[hh];
        }
        float* op = d_po + (size_t)base*32 + 2*(l & 3);
        #pragma unroll
        for (int j = 0; j < 4; j++)
            *(float2*)(op + 8*j) = make_float2(of[j][2*hh], of[j][2*hh+1]);
    }
}

// ---------------- C: combine + out-proj + residual + layernorm -----------
__global__ void kfinal(const float* __restrict__ x, const float* __restrict__ out_w,
                       const float* __restrict__ ln_g, const float* __restrict__ ln_b,
                       float* __restrict__ out) {
    int n = blockIdx.x, t = threadIdx.x;   // 256 threads
    __shared__ float so[128];
    __shared__ float red[256], red2[256];
    if (t < 128) {
        int h = t >> 5, d = t & 31;
        float Mx = -INFINITY;
        #pragma unroll 2
        for (int c = 0; c < CH_; c++)
            Mx = fmaxf(Mx, d_pm[(h*CH_ + c)*N_ + n]);
        float L = 0.f, oa = 0.f;
        #pragma unroll 2
        for (int c = 0; c < CH_; c++) {
            int b = (h*CH_ + c)*N_ + n;
            float e = __expf(d_pm[b] - Mx);
            L  = fmaf(d_pl[b], e, L);
            oa = fmaf(d_po[(size_t)b*32 + d], e, oa);
        }
        so[t] = oa / L;
    }
    __syncthreads();
    float r = x[n*256 + t];
    const float* wr = out_w + t*128;
    #pragma unroll 8
    for (int e = 0; e < 128; e++) r = fmaf(so[e], wr[e], r);
    red[t] = r; red2[t] = r*r;
    __syncthreads();
    for (int s = 128; s > 0; s >>= 1) {
        if (t < s) { red[t] += red[t + s]; red2[t] += red2[t + s]; }
        __syncthreads();
    }
    float mu  = red[0] * (1.f/256.f);
    float var = red2[0] * (1.f/256.f) - mu*mu;
    float inv = rsqrtf(var + 1e-5f);
    out[n*256 + t] = (r - mu) * inv * ln_g[t] + ln_b[t];
}

// ---------------- launch --------------------------------------------------
extern "C" void kernel_launch(void* const* d_in, const int* in_sizes, int n_in,
                              void* d_out, int out_size) {
    const float* x       = (const float*)d_in[0];
    const float* y       = (const float*)d_in[1];
    const float* x_pos   = (const float*)d_in[2];
    const float* y_pos   = (const float*)d_in[3];
    const float* theta_w = (const float*)d_in[4];
    const float* phi_w   = (const float*)d_in[5];
    const float* g_w     = (const float*)d_in[6];
    const float* q_w1    = (const float*)d_in[7];
    const float* q_b1    = (const float*)d_in[8];
    const float* q_w2    = (const float*)d_in[9];
    const float* q_b2    = (const float*)d_in[10];
    const float* k_w1    = (const float*)d_in[11];
    const float* k_b1    = (const float*)d_in[12];
    const float* k_w2    = (const float*)d_in[13];
    const float* k_b2    = (const float*)d_in[14];
    const float* out_w   = (const float*)d_in[15];
    const float* ln_g    = (const float*)d_in[16];
    const float* ln_b    = (const float*)d_in[17];
    float* out = (float*)d_out;

    cudaFuncSetAttribute(kprep, cudaFuncAttributeMaxDynamicSharedMemorySize, PREP_SMF*4);
    cudaFuncSetAttribute(kattn, cudaFuncAttributeMaxDynamicSharedMemorySize, SM_TOT);

    kprep<<<168, 256, PREP_SMF*4>>>(x, y, x_pos, theta_w, phi_w, g_w,
                                    q_w1, q_b1, q_w2, q_b2, k_w2, k_b2);
    kattn<<<148, 512, SM_TOT>>>(x_pos, y_pos, k_w1, k_b1);
    kfinal<<<256, 256>>>(x, out_w, ln_g, ln_b, out);
}

// round 17
// speedup vs baseline: 3.6438x; 1.0071x over previous
#include <cuda_runtime.h>
#include <cuda_bf16.h>
#include <stdint.h>
#include <math.h>

#define N_  256
#define M_  256
#define D_  256
#define E_  128
#define H_  4
#define HD_ 32
#define P_  64
#define CH_ 37    // key chunks per head (34 chunks of 7 tiles + 3 of 6)

typedef unsigned long long u64;

// ---------------- tensor-core helpers (bf16 m16n8k16) ---------------------
__device__ __forceinline__ uint32_t s2u(const void* p) {
    return (uint32_t)__cvta_generic_to_shared(p);
}
__device__ __forceinline__ void ldsm4(uint32_t& r0, uint32_t& r1, uint32_t& r2, uint32_t& r3, uint32_t a) {
    asm volatile("ldmatrix.sync.aligned.m8n8.x4.shared.b16 {%0,%1,%2,%3}, [%4];"
        : "=r"(r0), "=r"(r1), "=r"(r2), "=r"(r3) : "r"(a));
}
__device__ __forceinline__ void ldsm4t(uint32_t& r0, uint32_t& r1, uint32_t& r2, uint32_t& r3, uint32_t a) {
    asm volatile("ldmatrix.sync.aligned.m8n8.x4.trans.shared.b16 {%0,%1,%2,%3}, [%4];"
        : "=r"(r0), "=r"(r1), "=r"(r2), "=r"(r3) : "r"(a));
}
__device__ __forceinline__ void mma16816(float* c, const uint32_t* a, uint32_t b0, uint32_t b1) {
    asm volatile("mma.sync.aligned.m16n8k16.row.col.f32.bf16.bf16.f32 "
        "{%0,%1,%2,%3}, {%4,%5,%6,%7}, {%8,%9}, {%0,%1,%2,%3};"
        : "+f"(c[0]), "+f"(c[1]), "+f"(c[2]), "+f"(c[3])
        : "r"(a[0]), "r"(a[1]), "r"(a[2]), "r"(a[3]), "r"(b0), "r"(b1));
}
__device__ __forceinline__ uint32_t cvt2bf(float lo, float hi) {
    uint32_t r; asm("cvt.rn.bf16x2.f32 %0, %1, %2;" : "=r"(r) : "f"(hi), "f"(lo)); return r;
}
__device__ __forceinline__ float bf_lo(uint32_t p) { return __uint_as_float(p << 16); }
__device__ __forceinline__ float bf_hi(uint32_t p) { return __uint_as_float(p & 0xffff0000u); }

// ---------------- device scratch (static, no allocations) ----------------
__device__ float d_q[N_*E_];
__device__ float d_phix[N_*E_], d_nphiy[M_*E_];    // nphiy/ngy NEGATED
__device__ float d_gx[N_*E_],  d_ngy[M_*E_];
__device__ float d_Wkp[E_*P_], d_Wkg[E_*P_];
__device__ float d_bkp[E_],    d_bkg[E_];
__device__ float d_pm[H_*CH_*N_], d_pl[H_*CH_*N_];
__device__ float d_po[H_*CH_*N_*HD_];

__device__ __forceinline__ void chunk_range(int c, int& t0, int& t1) {
    if (c < 34) { t0 = 7*c;            t1 = t0 + 7; }
    else        { t0 = 238 + 6*(c-34); t1 = t0 + 6; }
}

// ---------------- A: fused prep ------------------------------------------
// grid 57, 256 threads, dynamic smem (59776 B).
// blocks [0,40): tiled gemm jobs (5 jobs x 8 row-tiles, job 0 inlines qpe)
// blocks [40,56): fold tiles (2 targets x 8 e-tiles of 16 rows)
// block  56:      bias folds (bkp / bkg)
// gemm smem float offsets: ws@0 (128*65), xs@8320 (32*65), qpe@10400 (32*130),
//                          w1s@14560(192), b1s@14752(64), b2s@14816(128)
#define PREP_SMF 14944
__global__ void __launch_bounds__(256)
kprep(const float* __restrict__ x, const float* __restrict__ y,
      const float* __restrict__ x_pos,
      const float* __restrict__ theta_w, const float* __restrict__ phi_w,
      const float* __restrict__ g_w,
      const float* __restrict__ q_w1, const float* __restrict__ q_b1,
      const float* __restrict__ q_w2, const float* __restrict__ q_b2,
      const float* __restrict__ k_w2, const float* __restrict__ k_b2) {
    int b = blockIdx.x, t = threadIdx.x;
    extern __shared__ float sp[];

    if (b >= 56) {                    // -------- bias folds --------
        // stage k_b2 (128 floats), then each thread does one e-row dot
        if (t < 128) sp[t] = k_b2[t];
        __syncthreads();
        int e = t & 127, which = t >> 7;
        const float* Wsrc = which ? g_w : phi_w;
        float* outb = which ? d_bkg : d_bkp;
        const float4* row = (const float4*)(Wsrc + e*384 + 256);
        float a0 = 0.f, a1 = 0.f, a2 = 0.f, a3 = 0.f;
        #pragma unroll
        for (int i = 0; i < 32; i++) {
            float4 v = row[i];
            a0 = fmaf(v.x, sp[4*i],   a0);
            a1 = fmaf(v.y, sp[4*i+1], a1);
            a2 = fmaf(v.z, sp[4*i+2], a2);
            a3 = fmaf(v.w, sp[4*i+3], a3);
        }
        outb[e] = (a0 + a1) + (a2 + a3);
        return;
    }

    if (b >= 40) {                    // -------- fold tiles (smem GEMM) ----
        int b2 = b - 40;              // 0..15
        int which = b2 >> 3;          // 0 = phi (Wkp), 1 = g (Wkg)
        int e0 = (b2 & 7) * 16;
        const float* Wsrc = which ? g_w : phi_w;
        float* out = which ? d_Wkg : d_Wkp;
        float* kws = sp;              // [128][65]
        float* as  = sp + 8320;       // [16][130]
        #pragma unroll 4
        for (int i = t; i < 8192; i += 256)
            kws[(i >> 6)*65 + (i & 63)] = k_w2[i];
        #pragma unroll 2
        for (int i = t; i < 2048; i += 256) {
            int r = i >> 7, cx = i & 127;
            as[r*130 + cx] = Wsrc[(e0 + r)*384 + 256 + cx];
        }
        __syncthreads();
        int p = t & 63, rg = t >> 6;  // 64 p-cols x 4 row-groups
        float acc[4] = {0.f, 0.f, 0.f, 0.f};
        #pragma unroll 4
        for (int ep = 0; ep < 128; ep++) {
            float wv = kws[ep*65 + p];
            acc[0] = fmaf(as[(rg*4+0)*130 + ep], wv, acc[0]);
            acc[1] = fmaf(as[(rg*4+1)*130 + ep], wv, acc[1]);
            acc[2] = fmaf(as[(rg*4+2)*130 + ep], wv, acc[2]);
            acc[3] = fmaf(as[(rg*4+3)*130 + ep], wv, acc[3]);
        }
        #pragma unroll
        for (int i = 0; i < 4; i++)
            out[(e0 + rg*4 + i)*64 + p] = acc[i];
        return;
    }

    // -------- tiled gemm jobs --------
    float* ws  = sp;
    float* xs  = sp + 8320;
    float* qpe = sp + 10400;
    float* w1s = sp + 14560;
    float* b1s = sp + 14752;
    float* b2s = sp + 14816;

    int job = b >> 3, rt = b & 7, n0 = rt * 32;
    const float* W   = (job == 0) ? theta_w : (job <= 2 ? phi_w : g_w);
    const float* src = (job == 2 || job == 4) ? y : x;
    int   K    = (job == 0) ? 384 : 256;
    float mult = (job == 0) ? 0.17677669529663687f
               : (job == 2 || job == 4) ? -1.f : 1.f;
    float* out = (job == 0) ? d_q : (job == 1) ? d_phix : (job == 2) ? d_nphiy
               : (job == 3) ? d_gx : d_ngy;

    int ce = t & 31, rg = t >> 5;

    if (job == 0) {                   // inline pos-MLP embedding
        #pragma unroll 4
        for (int i = t; i < 8192; i += 256) {
            int e = i >> 6, p = i & 63;
            ws[e*65 + p] = q_w2[i];
        }
        if (t < 192) w1s[t] = q_w1[t];
        if (t < 64)  b1s[t] = q_b1[t];
        if (t < 128) b2s[t] = q_b2[t];
        __syncthreads();
        #pragma unroll 2
        for (int i = t; i < 2048; i += 256) {
            int n = i >> 6, p = i & 63;
            float xp0 = x_pos[(n0+n)*3], xp1 = x_pos[(n0+n)*3+1], xp2 = x_pos[(n0+n)*3+2];
            xs[n*65 + p] = fmaxf(0.f, fmaf(w1s[p*3], xp0, fmaf(w1s[p*3+1], xp1,
                                  fmaf(w1s[p*3+2], xp2, b1s[p]))));
        }
        __syncthreads();
        float acc[4][4];
        #pragma unroll
        for (int i = 0; i < 4; i++)
            #pragma unroll
            for (int j = 0; j < 4; j++) acc[i][j] = b2s[ce + 32*j];
        #pragma unroll 4
        for (int p = 0; p < 64; p++) {
            float w0 = ws[(ce     )*65 + p], w1 = ws[(ce+32)*65 + p];
            float w2 = ws[(ce+64)*65 + p],  w3 = ws[(ce+96)*65 + p];
            #pragma unroll
            for (int i = 0; i < 4; i++) {
                float xv = xs[(rg*4 + i)*65 + p];
                acc[i][0] = fmaf(xv, w0, acc[i][0]);
                acc[i][1] = fmaf(xv, w1, acc[i][1]);
                acc[i][2] = fmaf(xv, w2, acc[i][2]);
                acc[i][3] = fmaf(xv, w3, acc[i][3]);
            }
        }
        __syncthreads();
        #pragma unroll
        for (int i = 0; i < 4; i++)
            #pragma unroll
            for (int j = 0; j < 4; j++)
                qpe[(rg*4 + i)*130 + ce + 32*j] = acc[i][j];
        __syncthreads();
    }

    float acc[4][4];
    #pragma unroll
    for (int i = 0; i < 4; i++)
        #pragma unroll
        for (int j = 0; j < 4; j++) acc[i][j] = 0.f;

    for (int k0 = 0; k0 < K; k0 += 64) {
        #pragma unroll 4
        for (int i = t; i < 8192; i += 256) {
            int e = i >> 6, k = i & 63;
            ws[e*65 + k] = W[e*384 + k0 + k];
        }
        #pragma unroll 2
        for (int i = t; i < 2048; i += 256) {
            int n = i >> 6, k = i & 63;
            float v;
            if (job == 0 && k0 >= 256) v = qpe[n*130 + (k0 - 256) + k];
            else                       v = src[(n0+n)*256 + k0 + k];
            xs[n*65 + k] = v;
        }
        __syncthreads();
        #pragma unroll 4
        for (int k = 0; k < 64; k++) {
            float w0 = ws[(ce     )*65 + k], w1 = ws[(ce+32)*65 + k];
            float w2 = ws[(ce+64)*65 + k],  w3 = ws[(ce+96)*65 + k];
            #pragma unroll
            for (int i = 0; i < 4; i++) {
                float xv = xs[(rg*4 + i)*65 + k];
                acc[i][0] = fmaf(xv, w0, acc[i][0]);
                acc[i][1] = fmaf(xv, w1, acc[i][1]);
                acc[i][2] = fmaf(xv, w2, acc[i][2]);
                acc[i][3] = fmaf(xv, w3, acc[i][3]);
            }
        }
        __syncthreads();
    }
    #pragma unroll
    for (int i = 0; i < 4; i++)
        #pragma unroll
        for (int j = 0; j < 4; j++)
            out[(n0 + rg*4 + i)*128 + ce + 32*j] = acc[i][j] * mult;
}

// ---------------- B: full-mma kattn (512 thr, 148 CTAs, CH=37) -----------
// smem byte layout:
//   K    bf16[256][40] @ 0      (rows stride 80B)
//   V    bf16[256][40] @ 20480
//   H1   bf16[256][72] @ 40960  (rows stride 144B; also Q staging at prologue)
//   WK   bf16[32][72]  @ 77824  (Wkp head slice [dim][p], stride 144B)
//   WV   bf16[32][72]  @ 82432
//   kw1s f32[192]      @ 87040
//   kb1s f32[64]       @ 87808
//   cscK f32[32]       @ 88064
//   cscV f32[32]       @ 88192    total 88320
#define OFF_V   20480
#define OFF_H1  40960
#define OFF_WK  77824
#define OFF_WV  82432
#define OFF_KW1 87040
#define OFF_KB1 87808
#define OFF_CSK 88064
#define OFF_CSV 88192
#define SM_TOT  88320

__global__ void __launch_bounds__(512, 1)
kattn(const float* __restrict__ x_pos, const float* __restrict__ y_pos,
      const float* __restrict__ k_w1, const float* __restrict__ k_b1) {
    extern __shared__ char smb[];
    float* kw1s = (float*)(smb + OFF_KW1);
    float* kb1s = (float*)(smb + OFF_KB1);
    float* cscK = (float*)(smb + OFF_CSK);
    float* cscV = (float*)(smb + OFF_CSV);
    uint32_t sbase = s2u(smb);

    int bid = blockIdx.x, t = threadIdx.x;
    int h = bid / CH_, c = bid % CH_;
    int t0, t1; chunk_range(c, t0, t1);
    int l = t & 31, wv = t >> 5;

    // ---- stage weights bf16 [dim][p] ----
    for (int i = t; i < 1024; i += 512) {
        int d = i >> 5, pp = i & 31;
        float2 vk = *(const float2*)(d_Wkp + (h*32 + d)*64 + 2*pp);
        float2 vg = *(const float2*)(d_Wkg + (h*32 + d)*64 + 2*pp);
        *(uint32_t*)(smb + OFF_WK + d*144 + pp*4) = cvt2bf(vk.x, vk.y);
        *(uint32_t*)(smb + OFF_WV + d*144 + pp*4) = cvt2bf(vg.x, vg.y);
    }
    for (int i = t; i < 192; i += 512) kw1s[i] = k_w1[i];
    if (t < 64) kb1s[t] = k_b1[t];

    // ---- stage Q bf16 into H1 region (stride 144) ----
    if (t < 256) {
        const float4* qp = (const float4*)(d_q + t*E_ + h*HD_);
        uint32_t wb[16];
        #pragma unroll
        for (int i = 0; i < 8; i++) {
            float4 v = qp[i];
            wb[2*i]   = cvt2bf(v.x, v.y);
            wb[2*i+1] = cvt2bf(v.z, v.w);
        }
        uint4* dst = (uint4*)(smb + OFF_H1 + t*144);
        #pragma unroll
        for (int i = 0; i < 4; i++)
            dst[i] = make_uint4(wb[4*i], wb[4*i+1], wb[4*i+2], wb[4*i+3]);
    }
    __syncthreads();

    // ---- Q fragments (1 mtile of 16 rows per warp) ----
    uint32_t qf[2][4];
    {
        int qrow = wv*16 + (l & 7) + ((l >> 3) & 1) * 8;
        uint32_t col = ((l >> 4) & 1) * 16;
        ldsm4(qf[0][0], qf[0][1], qf[0][2], qf[0][3], sbase + OFF_H1 + qrow*144 + col);
        ldsm4(qf[1][0], qf[1][1], qf[1][2], qf[1][3], sbase + OFF_H1 + qrow*144 + col + 32);
    }
    // ---- phix / gx base fragments (bf16x2 pairs, tile-invariant, 16 regs) ----
    uint32_t phixp[8], gxp[8];
    #pragma unroll
    for (int hh = 0; hh < 2; hh++)
        #pragma unroll
        for (int j = 0; j < 4; j++) {
            int row  = wv*16 + (l >> 2) + 8*hh;
            int colf = h*32 + 2*(l & 3) + 8*j;
            float2 vp = *(const float2*)(d_phix + row*128 + colf);
            float2 vg = *(const float2*)(d_gx   + row*128 + colf);
            phixp[hh*4+j] = cvt2bf(vp.x, vp.y);
            gxp[hh*4+j]   = cvt2bf(vg.x, vg.y);
        }
    __syncthreads();   // Q frags consumed before H1 overwritten

    float of[4][4];
    #pragma unroll
    for (int j = 0; j < 4; j++)
        #pragma unroll
        for (int k = 0; k < 4; k++) of[j][k] = 0.f;
    float mst[2] = {-INFINITY, -INFINITY}, lst[2] = {0.f, 0.f};

    int hrow = t & 255, phalf = t >> 8;
    float xp0 = x_pos[hrow*3], xp1 = x_pos[hrow*3+1], xp2 = x_pos[hrow*3+2];

    #pragma unroll 1
    for (int m = t0; m < t1; ++m) {
        // col scalars: bias - phi_y[m] (nphiy already negated)
        if (t < 32)       cscK[t]    = d_bkp[h*32 + t]      + d_nphiy[m*128 + h*32 + t];
        else if (t < 64)  cscV[t-32] = d_bkg[h*32 + (t-32)] + d_ngy[m*128 + h*32 + (t-32)];

        // ---- h1 gen: row hrow, p-range phalf*32..+31, bf16 to smem ----
        {
            float r0 = xp0 - y_pos[m*3], r1 = xp1 - y_pos[m*3+1], r2 = xp2 - y_pos[m*3+2];
            uint32_t hb[16];
            #pragma unroll
            for (int pp = 0; pp < 16; pp++) {
                int p = phalf*32 + 2*pp;
                float a = fmaxf(0.f, fmaf(kw1s[p*3],     r0, fmaf(kw1s[p*3+1],     r1,
                               fmaf(kw1s[p*3+2],     r2, kb1s[p]))));
                float b = fmaxf(0.f, fmaf(kw1s[p*3+3],   r0, fmaf(kw1s[p*3+4],     r1,
                               fmaf(kw1s[p*3+5],     r2, kb1s[p+1]))));
                hb[pp] = cvt2bf(a, b);
            }
            uint4* hd = (uint4*)(smb + OFF_H1 + hrow*144 + phalf*64);
            #pragma unroll
            for (int i = 0; i < 4; i++)
                hd[i] = make_uint4(hb[4*i], hb[4*i+1], hb[4*i+2], hb[4*i+3]);
        }
        __syncthreads();

        // ---- A frags: h1 rows for this warp's 16 keys (shared K/V) ----
        uint32_t af[4][4];
        {
            int arow = wv*16 + (l & 7) + ((l >> 3) & 1) * 8;
            uint32_t acol = ((l >> 4) & 1) * 16;
            #pragma unroll
            for (int u = 0; u < 4; u++)
                ldsm4(af[u][0], af[u][1], af[u][2], af[u][3],
                      sbase + OFF_H1 + arow*144 + acol + 32*u);
        }
        // ---- K then V generation via mma ----
        #pragma unroll
        for (int pass = 0; pass < 2; pass++) {
            uint32_t woff = pass ? OFF_WV : OFF_WK;
            const float* csc = pass ? cscV : cscK;
            const uint32_t* bfr = pass ? gxp : phixp;
            uint32_t koff = pass ? OFF_V : 0;
            float cf[4][4];
            #pragma unroll
            for (int j = 0; j < 4; j++)
                #pragma unroll
                for (int k = 0; k < 4; k++) cf[j][k] = 0.f;
            #pragma unroll
            for (int j = 0; j < 4; j++) {
                uint32_t b0,b1,b2,b3,b4,b5,b6,b7;
                int wrow = 8*j + (l & 7);
                uint32_t wcol = (l >> 3) * 16;
                ldsm4(b0,b1,b2,b3, sbase + woff + wrow*144 + wcol);
                ldsm4(b4,b5,b6,b7, sbase + woff + wrow*144 + wcol + 64);
                mma16816(cf[j], af[0], b0, b1);
                mma16816(cf[j], af[1], b2, b3);
                mma16816(cf[j], af[2], b4, b5);
                mma16816(cf[j], af[3], b6, b7);
            }
            #pragma unroll
            for (int j = 0; j < 4; j++) {
                float2 cs = *(const float2*)(csc + 2*(l & 3) + 8*j);
                #pragma unroll
                for (int hh = 0; hh < 2; hh++) {
                    uint32_t bp = bfr[hh*4+j];
                    float v0 = cf[j][2*hh]   + bf_lo(bp) + cs.x;
                    float v1 = cf[j][2*hh+1] + bf_hi(bp) + cs.y;
                    int row = wv*16 + (l >> 2) + 8*hh;
                    *(uint32_t*)(smb + koff + row*80 + 4*(l & 3) + 16*j) = cvt2bf(v0, v1);
                }
            }
        }
        __syncthreads();

        // ---- attention over this 256-key tile, 32-key blocks ----
        #pragma unroll 1
        for (int kb0 = 0; kb0 < 256; kb0 += 32) {
            float sf[4][4];
            #pragma unroll
            for (int j = 0; j < 4; j++)
                #pragma unroll
                for (int k = 0; k < 4; k++) sf[j][k] = 0.f;
            #pragma unroll
            for (int j = 0; j < 4; j++) {
                uint32_t b0, b1, b2, b3;
                int krow = kb0 + 8*j + (l & 7);
                ldsm4(b0, b1, b2, b3, sbase + krow*80 + (l >> 3)*16);
                mma16816(sf[j], qf[0], b0, b1);
                mma16816(sf[j], qf[1], b2, b3);
            }
            #pragma unroll
            for (int hh = 0; hh < 2; hh++) {
                float bm = sf[0][2*hh];
                #pragma unroll
                for (int j = 0; j < 4; j++) {
                    bm = fmaxf(bm, sf[j][2*hh]);
                    bm = fmaxf(bm, sf[j][2*hh+1]);
                }
                bm = fmaxf(bm, __shfl_xor_sync(0xffffffffu, bm, 1));
                bm = fmaxf(bm, __shfl_xor_sync(0xffffffffu, bm, 2));
                float mn = fmaxf(mst[hh], bm);
                float sc = __expf(mst[hh] - mn);
                mst[hh] = mn;
                float ps = 0.f;
                #pragma unroll
                for (int j = 0; j < 4; j++) {
                    float p0 = __expf(sf[j][2*hh]   - mn);
                    float p1 = __expf(sf[j][2*hh+1] - mn);
                    sf[j][2*hh] = p0; sf[j][2*hh+1] = p1;
                    ps += p0 + p1;
                }
                ps += __shfl_xor_sync(0xffffffffu, ps, 1);
                ps += __shfl_xor_sync(0xffffffffu, ps, 2);
                lst[hh] = lst[hh]*sc + ps;
                #pragma unroll
                for (int j = 0; j < 4; j++) {
                    of[j][2*hh]   *= sc;
                    of[j][2*hh+1] *= sc;
                }
            }
            #pragma unroll
            for (int u = 0; u < 2; u++) {
                uint32_t c0, c1, c2, c3, e0, e1, e2, e3;
                int kr = kb0 + 16*u + (l & 7);
                ldsm4t(c0, c1, c2, c3, sbase + OFF_V + kr*80     + (l >> 3)*16);
                ldsm4t(e0, e1, e2, e3, sbase + OFF_V + (kr+8)*80 + (l >> 3)*16);
                uint32_t pa[4];
                pa[0] = cvt2bf(sf[2*u][0],   sf[2*u][1]);
                pa[1] = cvt2bf(sf[2*u][2],   sf[2*u][3]);
                pa[2] = cvt2bf(sf[2*u+1][0], sf[2*u+1][1]);
                pa[3] = cvt2bf(sf[2*u+1][2], sf[2*u+1][3]);
                mma16816(of[0], pa, c0, e0);
                mma16816(of[1], pa, c1, e1);
                mma16816(of[2], pa, c2, e2);
                mma16816(of[3], pa, c3, e3);
            }
        }
    }

    // ---- epilogue: partial stats + unnormalized O ----
    #pragma unroll
    for (int hh = 0; hh < 2; hh++) {
        int qrow = wv*16 + (l >> 2) + 8*hh;
        int base = (h*CH_ + c)*N_ + qrow;
        if ((l & 3) == 0) {
            d_pm[base] = mst[hh];
            d_pl[base] = lst[hh];
        }
        float* op = d_po + (size_t)base*32 + 2*(l & 3);
        #pragma unroll
        for (int j = 0; j < 4; j++)
            *(float2*)(op + 8*j) = make_float2(of[j][2*hh], of[j][2*hh+1]);
    }
}

// ---------------- C: combine + out-proj + residual + layernorm -----------
__global__ void kfinal(const float* __restrict__ x, const float* __restrict__ out_w,
                       const float* __restrict__ ln_g, const float* __restrict__ ln_b,
                       float* __restrict__ out) {
    int n = blockIdx.x, t = threadIdx.x;   // 256 threads
    __shared__ float so[128];
    __shared__ float red[256], red2[256];
    if (t < 128) {
        int h = t >> 5, d = t & 31;
        float Mx = -INFINITY;
        #pragma unroll 4
        for (int c = 0; c < CH_; c++)
            Mx = fmaxf(Mx, d_pm[(h*CH_ + c)*N_ + n]);
        float L = 0.f, oa = 0.f;
        #pragma unroll 4
        for (int c = 0; c < CH_; c++) {
            int b = (h*CH_ + c)*N_ + n;
            float e = __expf(d_pm[b] - Mx);
            L  = fmaf(d_pl[b], e, L);
            oa = fmaf(d_po[(size_t)b*32 + d], e, oa);
        }
        so[t] = oa / L;
    }
    __syncthreads();
    float r = x[n*256 + t];
    const float* wr = out_w + t*128;
    #pragma unroll 8
    for (int e = 0; e < 128; e++) r = fmaf(so[e], wr[e], r);
    red[t] = r; red2[t] = r*r;
    __syncthreads();
    for (int s = 128; s > 0; s >>= 1) {
        if (t < s) { red[t] += red[t + s]; red2[t] += red2[t + s]; }
        __syncthreads();
    }
    float mu  = red[0] * (1.f/256.f);
    float var = red2[0] * (1.f/256.f) - mu*mu;
    float inv = rsqrtf(var + 1e-5f);
    out[n*256 + t] = (r - mu) * inv * ln_g[t] + ln_b[t];
}

// ---------------- launch --------------------------------------------------
extern "C" void kernel_launch(void* const* d_in, const int* in_sizes, int n_in,
                              void* d_out, int out_size) {
    const float* x       = (const float*)d_in[0];
    const float* y       = (const float*)d_in[1];
    const float* x_pos   = (const float*)d_in[2];
    const float* y_pos   = (const float*)d_in[3];
    const float* theta_w = (const float*)d_in[4];
    const float* phi_w   = (const float*)d_in[5];
    const float* g_w     = (const float*)d_in[6];
    const float* q_w1    = (const float*)d_in[7];
    const float* q_b1    = (const float*)d_in[8];
    const float* q_w2    = (const float*)d_in[9];
    const float* q_b2    = (const float*)d_in[10];
    const float* k_w1    = (const float*)d_in[11];
    const float* k_b1    = (const float*)d_in[12];
    const float* k_w2    = (const float*)d_in[13];
    const float* k_b2    = (const float*)d_in[14];
    const float* out_w   = (const float*)d_in[15];
    const float* ln_g    = (const float*)d_in[16];
    const float* ln_b    = (const float*)d_in[17];
    float* out = (float*)d_out;

    cudaFuncSetAttribute(kprep, cudaFuncAttributeMaxDynamicSharedMemorySize, PREP_SMF*4);
    cudaFuncSetAttribute(kattn, cudaFuncAttributeMaxDynamicSharedMemorySize, SM_TOT);

    kprep<<<57, 256, PREP_SMF*4>>>(x, y, x_pos, theta_w, phi_w, g_w,
                                   q_w1, q_b1, q_w2, q_b2, k_w2, k_b2);
    kattn<<<148, 512, SM_TOT>>>(x_pos, y_pos, k_w1, k_b1);
    kfinal<<<256, 256>>>(x, out_w, ln_g, ln_b, out);
}